// round 2
// baseline (speedup 1.0000x reference)
#include <cuda_runtime.h>
#include <math.h>

#define EMBED   512
#define HEADS   8
#define HD      64
#define BB      2
#define NSEQ    4096
#define M_ROWS  (BB * NSEQ)          // 8192
#define QKV_COLS (3 * EMBED)         // 1536

// Scratch (allocation-free: __device__ globals)
__device__ float g_qkv[(size_t)M_ROWS * QKV_COLS];  // [B*N, 1536]
__device__ float g_att[(size_t)M_ROWS * EMBED];     // [B*N, 512]

// ---------------------------------------------------------------------------
// Generic GEMM: C[M,Nc] = A[M,K] @ W[Nc,K]^T + bias[Nc]
// Block tile 64x64, 256 threads, 4x4 micro-tile. Both operands transposed in
// smem (stride 68 keeps float4 rows 16B-aligned and write conflicts at 4-way).
// ---------------------------------------------------------------------------
__global__ __launch_bounds__(256) void gemm_bias_kernel(
    const float* __restrict__ A, const float* __restrict__ W,
    const float* __restrict__ bias, float* __restrict__ C,
    int M, int Nc, int K)
{
    __shared__ float At[64][68];
    __shared__ float Wt[64][68];

    const int tid = threadIdx.x;
    const int tx  = tid & 15;       // 0..15 -> 4 output cols each
    const int ty  = tid >> 4;       // 0..15 -> 4 output rows each
    const int m0  = blockIdx.x * 64;
    const int n0  = blockIdx.y * 64;

    float acc[4][4] = {};

    for (int k0 = 0; k0 < K; k0 += 64) {
        #pragma unroll
        for (int idx = tid; idx < 4096; idx += 256) {
            int r = idx >> 6;       // row within tile (m or n)
            int c = idx & 63;       // k within tile
            At[c][r] = A[(size_t)(m0 + r) * K + (k0 + c)];
            Wt[c][r] = W[(size_t)(n0 + r) * K + (k0 + c)];
        }
        __syncthreads();

        #pragma unroll 8
        for (int kk = 0; kk < 64; kk++) {
            float4 a4 = *(const float4*)&At[kk][ty * 4];
            float4 b4 = *(const float4*)&Wt[kk][tx * 4];
            float av[4] = {a4.x, a4.y, a4.z, a4.w};
            float bv[4] = {b4.x, b4.y, b4.z, b4.w};
            #pragma unroll
            for (int i = 0; i < 4; i++)
                #pragma unroll
                for (int j = 0; j < 4; j++)
                    acc[i][j] += av[i] * bv[j];
        }
        __syncthreads();
    }

    #pragma unroll
    for (int i = 0; i < 4; i++) {
        int m = m0 + ty * 4 + i;
        #pragma unroll
        for (int j = 0; j < 4; j++) {
            int n = n0 + tx * 4 + j;
            C[(size_t)m * Nc + n] = acc[i][j] + bias[n];
        }
    }
}

// ---------------------------------------------------------------------------
// Flash attention (causal), fp32. One block = 64 q-rows of one (b,h).
// Online softmax in registers. Smem (dynamic, 51200B):
//   Qt[64][68]  : Q transposed ([d][r]) -> float4 broadcast reads
//   KtP[64][68] : K transposed ([d][r]) for S phase; reused as P[r][j]
//   Vs[64][64]  : V natural ([r][d])
// ---------------------------------------------------------------------------
#define ATT_SMEM_BYTES ((2 * 64 * 68 + 64 * 64) * 4)

__global__ __launch_bounds__(256) void attn_kernel(
    const float* __restrict__ qkv, float* __restrict__ out)
{
    extern __shared__ float sm[];
    float (*Qt)[68] = (float(*)[68])sm;
    float (*KtP)[68] = (float(*)[68])(sm + 64 * 68);
    float (*Vs)[64] = (float(*)[64])(sm + 2 * 64 * 68);

    const int iq = blockIdx.x;   // q tile (64 rows)
    const int h  = blockIdx.y;
    const int b  = blockIdx.z;
    const int tid = threadIdx.x;
    const int tx  = tid & 15;
    const int ty  = tid >> 4;

    const size_t rs = QKV_COLS;
    const float* base = qkv + (size_t)b * NSEQ * rs + (size_t)h * HD;

    // Load Q tile transposed
    for (int idx = tid; idx < 4096; idx += 256) {
        int r = idx >> 6, d = idx & 63;
        Qt[d][r] = base[(size_t)(iq * 64 + r) * rs + d];
    }

    float mrow[4], lrow[4], o[4][4];
    #pragma unroll
    for (int i = 0; i < 4; i++) {
        mrow[i] = -1e30f; lrow[i] = 0.f;
        #pragma unroll
        for (int j = 0; j < 4; j++) o[i][j] = 0.f;
    }
    const float scale = 0.125f;   // D^-0.5, D=64

    for (int kt = 0; kt <= iq; kt++) {
        __syncthreads();   // previous-iteration P reads done before overwrite
        for (int idx = tid; idx < 4096; idx += 256) {
            int r = idx >> 6, d = idx & 63;
            size_t g = (size_t)(kt * 64 + r) * rs + d;
            KtP[d][r] = base[g + EMBED];       // K transposed
            Vs[r][d]  = base[g + 2 * EMBED];   // V natural
        }
        __syncthreads();

        // S = Q @ K^T (4x4 micro-tile in regs)
        float s[4][4] = {};
        #pragma unroll 8
        for (int kk = 0; kk < 64; kk++) {
            float4 q4 = *(const float4*)&Qt[kk][ty * 4];
            float4 k4 = *(const float4*)&KtP[kk][tx * 4];
            float qv[4] = {q4.x, q4.y, q4.z, q4.w};
            float kv[4] = {k4.x, k4.y, k4.z, k4.w};
            #pragma unroll
            for (int i = 0; i < 4; i++)
                #pragma unroll
                for (int j = 0; j < 4; j++)
                    s[i][j] += qv[i] * kv[j];
        }

        // scale + causal mask (diagonal tile only)
        if (kt == iq) {
            #pragma unroll
            for (int i = 0; i < 4; i++)
                #pragma unroll
                for (int j = 0; j < 4; j++) {
                    int rg = ty * 4 + i, cg = tx * 4 + j;
                    s[i][j] = (cg <= rg) ? s[i][j] * scale : -1e30f;
                }
        } else {
            #pragma unroll
            for (int i = 0; i < 4; i++)
                #pragma unroll
                for (int j = 0; j < 4; j++) s[i][j] *= scale;
        }

        // online softmax per row (16 tx-lanes share a row; xor-shuffle reduce)
        #pragma unroll
        for (int i = 0; i < 4; i++) {
            float rm = s[i][0];
            #pragma unroll
            for (int j = 1; j < 4; j++) rm = fmaxf(rm, s[i][j]);
            #pragma unroll
            for (int off = 8; off >= 1; off >>= 1)
                rm = fmaxf(rm, __shfl_xor_sync(0xffffffffu, rm, off));
            float mn = fmaxf(mrow[i], rm);
            float alpha = __expf(mrow[i] - mn);
            float rsum = 0.f;
            #pragma unroll
            for (int j = 0; j < 4; j++) {
                s[i][j] = __expf(s[i][j] - mn);
                rsum += s[i][j];
            }
            #pragma unroll
            for (int off = 8; off >= 1; off >>= 1)
                rsum += __shfl_xor_sync(0xffffffffu, rsum, off);
            lrow[i] = lrow[i] * alpha + rsum;
            mrow[i] = mn;
            #pragma unroll
            for (int j = 0; j < 4; j++) o[i][j] *= alpha;
        }

        __syncthreads();   // all S reads of KtP done
        // write P into KtP buffer as [r][j] (stride 68)
        #pragma unroll
        for (int i = 0; i < 4; i++)
            #pragma unroll
            for (int j = 0; j < 4; j++)
                KtP[ty * 4 + i][tx * 4 + j] = s[i][j];
        __syncthreads();

        // O += P @ V
        #pragma unroll 8
        for (int kk = 0; kk < 64; kk++) {
            float pv[4];
            #pragma unroll
            for (int i = 0; i < 4; i++) pv[i] = KtP[ty * 4 + i][kk];
            float4 v4 = *(const float4*)&Vs[kk][tx * 4];
            float vv[4] = {v4.x, v4.y, v4.z, v4.w};
            #pragma unroll
            for (int i = 0; i < 4; i++)
                #pragma unroll
                for (int j = 0; j < 4; j++)
                    o[i][j] += pv[i] * vv[j];
        }
    }

    // epilogue: normalize and write [b][n][h*64+d]
    float* ob = out + ((size_t)b * NSEQ + (size_t)iq * 64) * EMBED + (size_t)h * HD;
    #pragma unroll
    for (int i = 0; i < 4; i++) {
        float inv = 1.f / lrow[i];
        #pragma unroll
        for (int j = 0; j < 4; j++)
            ob[(size_t)(ty * 4 + i) * EMBED + tx * 4 + j] = o[i][j] * inv;
    }
}

// ---------------------------------------------------------------------------
extern "C" void kernel_launch(void* const* d_in, const int* in_sizes, int n_in,
                              void* d_out, int out_size)
{
    // Identify inputs by element count (all distinct)
    const float *x = nullptr, *qkv_w = nullptr, *qkv_b = nullptr;
    const float *out_w = nullptr, *out_b = nullptr;
    for (int i = 0; i < n_in; i++) {
        switch (in_sizes[i]) {
            case M_ROWS * EMBED:        x     = (const float*)d_in[i]; break; // 4194304
            case EMBED * QKV_COLS:      qkv_w = (const float*)d_in[i]; break; // 786432
            case QKV_COLS:              qkv_b = (const float*)d_in[i]; break; // 1536
            case EMBED * EMBED:         out_w = (const float*)d_in[i]; break; // 262144
            case EMBED:                 out_b = (const float*)d_in[i]; break; // 512
            default: break; // mask (16777216) ignored: causal tril is hardcoded
        }
    }
    float* out = (float*)d_out;

    float *qkv_s, *att_s;
    cudaGetSymbolAddress((void**)&qkv_s, g_qkv);
    cudaGetSymbolAddress((void**)&att_s, g_att);

    cudaFuncSetAttribute(attn_kernel,
                         cudaFuncAttributeMaxDynamicSharedMemorySize,
                         ATT_SMEM_BYTES);

    // 1) QKV projection: [8192,512] @ [1536,512]^T -> [8192,1536]
    gemm_bias_kernel<<<dim3(M_ROWS / 64, QKV_COLS / 64), 256>>>(
        x, qkv_w, qkv_b, qkv_s, M_ROWS, QKV_COLS, EMBED);

    // 2) Causal flash attention -> [8192,512]
    attn_kernel<<<dim3(NSEQ / 64, HEADS, BB), 256, ATT_SMEM_BYTES>>>(qkv_s, att_s);

    // 3) Output projection: [8192,512] @ [512,512]^T -> d_out
    gemm_bias_kernel<<<dim3(M_ROWS / 64, EMBED / 64), 256>>>(
        att_s, out_w, out_b, out, M_ROWS, EMBED, EMBED);
}

// round 3
// speedup vs baseline: 3.2076x; 3.2076x over previous
#include <cuda_runtime.h>

#define EMBED   512
#define HEADS   8
#define HD      64
#define BB      2
#define NSEQ    4096
#define M_ROWS  (BB * NSEQ)          // 8192
#define QKV_COLS (3 * EMBED)         // 1536

// Scratch (allocation-free: __device__ globals)
__device__ float g_qkv[(size_t)M_ROWS * QKV_COLS];  // [B*N, 1536]
__device__ float g_att[(size_t)M_ROWS * EMBED];     // [B*N, 512]

// ---------------------------------------------------------------------------
// tf32 helpers
// ---------------------------------------------------------------------------
__device__ __forceinline__ unsigned int f2tf(float x) {
    unsigned int r;
    asm("cvt.rna.tf32.f32 %0, %1;" : "=r"(r) : "f"(x));
    return r;
}

__device__ __forceinline__ void mma8(float* c, const unsigned int* a,
                                     unsigned int b0, unsigned int b1) {
    asm volatile(
        "mma.sync.aligned.m16n8k8.row.col.f32.tf32.tf32.f32 "
        "{%0,%1,%2,%3}, {%4,%5,%6,%7}, {%8,%9}, {%0,%1,%2,%3};"
        : "+f"(c[0]), "+f"(c[1]), "+f"(c[2]), "+f"(c[3])
        : "r"(a[0]), "r"(a[1]), "r"(a[2]), "r"(a[3]), "r"(b0), "r"(b1));
}

// ---------------------------------------------------------------------------
// Split-tf32 GEMM: C[M,Nc] = A[M,K] @ W[Nc,K]^T + bias   (near-fp32 accurate)
// Block tile 128x128, 8 warps (4x2), warp tile 32x64, K-chunk 32.
// smem stride 36 -> conflict-free fragment reads.
// ---------------------------------------------------------------------------
#define GSM_PLANE (128 * 36)
#define GEMM_SMEM (4 * GSM_PLANE * 4)

__global__ __launch_bounds__(256) void gemm_tf32(
    const float* __restrict__ A, const float* __restrict__ W,
    const float* __restrict__ bias, float* __restrict__ C,
    int M, int Nc, int K)
{
    extern __shared__ unsigned int gsm[];
    unsigned int (*Ah)[36] = (unsigned int(*)[36])(gsm);
    unsigned int (*Al)[36] = (unsigned int(*)[36])(gsm + GSM_PLANE);
    unsigned int (*Wh)[36] = (unsigned int(*)[36])(gsm + 2 * GSM_PLANE);
    unsigned int (*Wl)[36] = (unsigned int(*)[36])(gsm + 3 * GSM_PLANE);

    const int tid = threadIdx.x;
    const int warp = tid >> 5, lane = tid & 31;
    const int wm = warp >> 1, wn = warp & 1;
    const int g = lane >> 2, tig = lane & 3;
    const int m0 = blockIdx.x * 128, n0 = blockIdx.y * 128;

    float acc[2][8][4] = {};

    for (int k0 = 0; k0 < K; k0 += 32) {
        __syncthreads();   // previous-iteration fragment reads done
        #pragma unroll
        for (int i = 0; i < 4; i++) {
            int f4 = tid + i * 256;          // 0..1023 float4 slots
            int r = f4 >> 3;                 // 8 float4 per 32-wide row
            int c4 = (f4 & 7) * 4;
            float4 va = *(const float4*)&A[(size_t)(m0 + r) * K + k0 + c4];
            float4 vw = *(const float4*)&W[(size_t)(n0 + r) * K + k0 + c4];
            float av[4] = {va.x, va.y, va.z, va.w};
            float wv[4] = {vw.x, vw.y, vw.z, vw.w};
            #pragma unroll
            for (int j = 0; j < 4; j++) {
                unsigned int h = f2tf(av[j]);
                Ah[r][c4 + j] = h;
                Al[r][c4 + j] = f2tf(av[j] - __uint_as_float(h));
                unsigned int h2 = f2tf(wv[j]);
                Wh[r][c4 + j] = h2;
                Wl[r][c4 + j] = f2tf(wv[j] - __uint_as_float(h2));
            }
        }
        __syncthreads();

        #pragma unroll
        for (int s = 0; s < 4; s++) {
            unsigned int ah[2][4], al[2][4];
            #pragma unroll
            for (int mt = 0; mt < 2; mt++) {
                int row = wm * 32 + mt * 16;
                ah[mt][0] = Ah[row + g][s * 8 + tig];
                ah[mt][1] = Ah[row + g + 8][s * 8 + tig];
                ah[mt][2] = Ah[row + g][s * 8 + tig + 4];
                ah[mt][3] = Ah[row + g + 8][s * 8 + tig + 4];
                al[mt][0] = Al[row + g][s * 8 + tig];
                al[mt][1] = Al[row + g + 8][s * 8 + tig];
                al[mt][2] = Al[row + g][s * 8 + tig + 4];
                al[mt][3] = Al[row + g + 8][s * 8 + tig + 4];
            }
            #pragma unroll
            for (int nt = 0; nt < 8; nt++) {
                int nc = wn * 64 + nt * 8;
                unsigned int bh0 = Wh[nc + g][s * 8 + tig];
                unsigned int bh1 = Wh[nc + g][s * 8 + tig + 4];
                unsigned int bl0 = Wl[nc + g][s * 8 + tig];
                unsigned int bl1 = Wl[nc + g][s * 8 + tig + 4];
                #pragma unroll
                for (int mt = 0; mt < 2; mt++) {
                    mma8(acc[mt][nt], al[mt], bh0, bh1);
                    mma8(acc[mt][nt], ah[mt], bl0, bl1);
                    mma8(acc[mt][nt], ah[mt], bh0, bh1);
                }
            }
        }
    }

    #pragma unroll
    for (int mt = 0; mt < 2; mt++) {
        int r0 = m0 + wm * 32 + mt * 16 + g;
        #pragma unroll
        for (int nt = 0; nt < 8; nt++) {
            int c0 = n0 + wn * 64 + nt * 8 + 2 * tig;
            float b0v = bias[c0], b1v = bias[c0 + 1];
            float2 v0 = make_float2(acc[mt][nt][0] + b0v, acc[mt][nt][1] + b1v);
            float2 v1 = make_float2(acc[mt][nt][2] + b0v, acc[mt][nt][3] + b1v);
            *(float2*)&C[(size_t)r0 * Nc + c0] = v0;
            *(float2*)&C[(size_t)(r0 + 8) * Nc + c0] = v1;
        }
    }
}

// ---------------------------------------------------------------------------
// Causal flash attention, tf32 tensor cores.
// Block = 128 q-rows of one (b,h); 8 warps, each an m16 stripe (softmax
// warp-local). K/V tiles of 64 keys in smem (stride 68: conflict-free frags).
// P roundtrips through warp-private smem rows (syncwarp only).
// ---------------------------------------------------------------------------
#define ATT_SMEM ((2 * 64 * 68 + 128 * 68) * 4)

__global__ __launch_bounds__(256) void attn_tf32(
    const float* __restrict__ qkv, float* __restrict__ out)
{
    extern __shared__ unsigned int sm[];
    unsigned int (*Ks)[68] = (unsigned int(*)[68])(sm);
    unsigned int (*Vs)[68] = (unsigned int(*)[68])(sm + 64 * 68);
    unsigned int (*Ps)[68] = (unsigned int(*)[68])(sm + 2 * 64 * 68);

    const int iq = blockIdx.x, h = blockIdx.y, b = blockIdx.z;
    const int tid = threadIdx.x;
    const int w = tid >> 5, lane = tid & 31;
    const int g = lane >> 2, tig = lane & 3;
    const float* base = qkv + (size_t)b * NSEQ * QKV_COLS + h * HD;
    const int q0 = iq * 128;
    const int rw = 16 * w;                  // warp's local row base

    // Stage Q (tf32) into Ps, then pull fragments into registers
    for (int idx = tid; idx < 128 * 64; idx += 256) {
        int r = idx >> 6, c = idx & 63;
        Ps[r][c] = f2tf(base[(size_t)(q0 + r) * QKV_COLS + c]);
    }
    __syncthreads();
    unsigned int qa[8][4];
    #pragma unroll
    for (int s = 0; s < 8; s++) {
        qa[s][0] = Ps[rw + g][8 * s + tig];
        qa[s][1] = Ps[rw + g + 8][8 * s + tig];
        qa[s][2] = Ps[rw + g][8 * s + tig + 4];
        qa[s][3] = Ps[rw + g + 8][8 * s + tig + 4];
    }

    float o[8][4] = {};
    float m0r = -1e30f, m1r = -1e30f, l0 = 0.f, l1 = 0.f;
    const int rowg0 = q0 + rw + g;          // global row of thread's row 0
    const int rowg1 = rowg0 + 8;
    const int ktmax = 2 * iq + 1;
    const float scale = 0.125f;             // 64^-0.5

    for (int kt = 0; kt <= ktmax; kt++) {
        __syncthreads();   // prior Ks/Vs reads (and Q frag reads) complete
        for (int idx = tid; idx < 4096; idx += 256) {
            int r = idx >> 6, c = idx & 63;
            size_t ga = (size_t)(kt * 64 + r) * QKV_COLS + c;
            Ks[r][c] = f2tf(base[ga + EMBED]);
            Vs[r][c] = f2tf(base[ga + 2 * EMBED]);
        }
        __syncthreads();

        if (kt * 64 > q0 + rw + 15) continue;   // tile fully masked for warp

        // ---- S = Q @ K^T ----
        float sc[8][4] = {};
        #pragma unroll
        for (int s = 0; s < 8; s++) {
            #pragma unroll
            for (int nt = 0; nt < 8; nt++) {
                unsigned int b0 = Ks[8 * nt + g][8 * s + tig];
                unsigned int b1 = Ks[8 * nt + g][8 * s + tig + 4];
                mma8(sc[nt], qa[s], b0, b1);
            }
        }

        // scale + causal mask (boundary tiles only)
        bool needmask = (kt * 64 + 63) > rowg0;
        #pragma unroll
        for (int nt = 0; nt < 8; nt++) {
            int c0 = kt * 64 + 8 * nt + 2 * tig;
            #pragma unroll
            for (int j = 0; j < 4; j++) sc[nt][j] *= scale;
            if (needmask) {
                if (c0 > rowg0)     sc[nt][0] = -1e30f;
                if (c0 + 1 > rowg0) sc[nt][1] = -1e30f;
                if (c0 > rowg1)     sc[nt][2] = -1e30f;
                if (c0 + 1 > rowg1) sc[nt][3] = -1e30f;
            }
        }

        // ---- online softmax (rows live in quads: shfl xor 1,2) ----
        float mx0 = -1e30f, mx1 = -1e30f;
        #pragma unroll
        for (int nt = 0; nt < 8; nt++) {
            mx0 = fmaxf(mx0, fmaxf(sc[nt][0], sc[nt][1]));
            mx1 = fmaxf(mx1, fmaxf(sc[nt][2], sc[nt][3]));
        }
        mx0 = fmaxf(mx0, __shfl_xor_sync(0xffffffffu, mx0, 1));
        mx0 = fmaxf(mx0, __shfl_xor_sync(0xffffffffu, mx0, 2));
        mx1 = fmaxf(mx1, __shfl_xor_sync(0xffffffffu, mx1, 1));
        mx1 = fmaxf(mx1, __shfl_xor_sync(0xffffffffu, mx1, 2));
        float mn0 = fmaxf(m0r, mx0), mn1 = fmaxf(m1r, mx1);
        float a0 = __expf(m0r - mn0), a1 = __expf(m1r - mn1);
        float s0 = 0.f, s1 = 0.f;
        #pragma unroll
        for (int nt = 0; nt < 8; nt++) {
            sc[nt][0] = __expf(sc[nt][0] - mn0);
            sc[nt][1] = __expf(sc[nt][1] - mn0);
            sc[nt][2] = __expf(sc[nt][2] - mn1);
            sc[nt][3] = __expf(sc[nt][3] - mn1);
            s0 += sc[nt][0] + sc[nt][1];
            s1 += sc[nt][2] + sc[nt][3];
        }
        s0 += __shfl_xor_sync(0xffffffffu, s0, 1);
        s0 += __shfl_xor_sync(0xffffffffu, s0, 2);
        s1 += __shfl_xor_sync(0xffffffffu, s1, 1);
        s1 += __shfl_xor_sync(0xffffffffu, s1, 2);
        l0 = l0 * a0 + s0;  l1 = l1 * a1 + s1;
        m0r = mn0;          m1r = mn1;
        #pragma unroll
        for (int nt = 0; nt < 8; nt++) {
            o[nt][0] *= a0; o[nt][1] *= a0;
            o[nt][2] *= a1; o[nt][3] *= a1;
        }

        // ---- P to warp-private smem rows, then O += P @ V ----
        #pragma unroll
        for (int nt = 0; nt < 8; nt++) {
            *(uint2*)&Ps[rw + g][8 * nt + 2 * tig] =
                make_uint2(f2tf(sc[nt][0]), f2tf(sc[nt][1]));
            *(uint2*)&Ps[rw + g + 8][8 * nt + 2 * tig] =
                make_uint2(f2tf(sc[nt][2]), f2tf(sc[nt][3]));
        }
        __syncwarp();
        #pragma unroll
        for (int s = 0; s < 8; s++) {
            unsigned int pa[4];
            pa[0] = Ps[rw + g][8 * s + tig];
            pa[1] = Ps[rw + g + 8][8 * s + tig];
            pa[2] = Ps[rw + g][8 * s + tig + 4];
            pa[3] = Ps[rw + g + 8][8 * s + tig + 4];
            #pragma unroll
            for (int nt = 0; nt < 8; nt++) {
                unsigned int b0 = Vs[8 * s + tig][8 * nt + g];
                unsigned int b1 = Vs[8 * s + tig + 4][8 * nt + g];
                mma8(o[nt], pa, b0, b1);
            }
        }
    }

    // epilogue
    float inv0 = 1.f / l0, inv1 = 1.f / l1;
    float* op0 = out + ((size_t)b * NSEQ + q0 + rw + g) * EMBED + h * HD;
    float* op1 = op0 + 8 * EMBED;
    #pragma unroll
    for (int nt = 0; nt < 8; nt++) {
        int c = 8 * nt + 2 * tig;
        *(float2*)&op0[c] = make_float2(o[nt][0] * inv0, o[nt][1] * inv0);
        *(float2*)&op1[c] = make_float2(o[nt][2] * inv1, o[nt][3] * inv1);
    }
}

// ---------------------------------------------------------------------------
extern "C" void kernel_launch(void* const* d_in, const int* in_sizes, int n_in,
                              void* d_out, int out_size)
{
    const float *x = nullptr, *qkv_w = nullptr, *qkv_b = nullptr;
    const float *out_w = nullptr, *out_b = nullptr;
    for (int i = 0; i < n_in; i++) {
        switch (in_sizes[i]) {
            case M_ROWS * EMBED:    x     = (const float*)d_in[i]; break;
            case EMBED * QKV_COLS:  qkv_w = (const float*)d_in[i]; break;
            case QKV_COLS:          qkv_b = (const float*)d_in[i]; break;
            case EMBED * EMBED:     out_w = (const float*)d_in[i]; break;
            case EMBED:             out_b = (const float*)d_in[i]; break;
            default: break;   // causal mask ignored (tril hardcoded)
        }
    }
    float* out = (float*)d_out;

    float *qkv_s, *att_s;
    cudaGetSymbolAddress((void**)&qkv_s, g_qkv);
    cudaGetSymbolAddress((void**)&att_s, g_att);

    static bool attr_done = false;
    if (!attr_done) {
        cudaFuncSetAttribute(gemm_tf32,
                             cudaFuncAttributeMaxDynamicSharedMemorySize, GEMM_SMEM);
        cudaFuncSetAttribute(attn_tf32,
                             cudaFuncAttributeMaxDynamicSharedMemorySize, ATT_SMEM);
        attr_done = true;
    }

    // 1) QKV projection: [8192,512] @ [1536,512]^T -> [8192,1536]
    gemm_tf32<<<dim3(M_ROWS / 128, QKV_COLS / 128), 256, GEMM_SMEM>>>(
        x, qkv_w, qkv_b, qkv_s, M_ROWS, QKV_COLS, EMBED);

    // 2) Causal flash attention -> [8192,512]
    attn_tf32<<<dim3(NSEQ / 128, HEADS, BB), 256, ATT_SMEM>>>(qkv_s, att_s);

    // 3) Output projection: [8192,512] @ [512,512]^T -> d_out
    gemm_tf32<<<dim3(M_ROWS / 128, EMBED / 128), 256, GEMM_SMEM>>>(
        att_s, out_w, out_b, out, M_ROWS, EMBED, EMBED);
}

// round 4
// speedup vs baseline: 4.4835x; 1.3978x over previous
#include <cuda_runtime.h>

#define EMBED   512
#define HEADS   8
#define HD      64
#define BB      2
#define NSEQ    4096
#define M_ROWS  (BB * NSEQ)          // 8192
#define QKV_COLS (3 * EMBED)         // 1536

// Scratch (allocation-free: __device__ globals)
__device__ float g_qkv[(size_t)M_ROWS * QKV_COLS];  // [B*N, 1536]
__device__ float g_att[(size_t)M_ROWS * EMBED];     // [B*N, 512]

// ---------------------------------------------------------------------------
// helpers
// ---------------------------------------------------------------------------
__device__ __forceinline__ unsigned int f2tf(float x) {
    unsigned int r;
    asm("cvt.rna.tf32.f32 %0, %1;" : "=r"(r) : "f"(x));
    return r;
}
__device__ __forceinline__ float ex2(float x) {
    float y;
    asm("ex2.approx.ftz.f32 %0, %1;" : "=f"(y) : "f"(x));
    return y;
}
// pack two floats to bf16x2 (v0 -> low half, v1 -> high half)
__device__ __forceinline__ unsigned int packbf(float v0, float v1) {
    unsigned int r;
    asm("cvt.rn.bf16x2.f32 %0, %1, %2;" : "=r"(r) : "f"(v1), "f"(v0));
    return r;
}
// split pair into hi word (bf16 round) + lo word (residual bf16)
__device__ __forceinline__ void split2(float v0, float v1,
                                       unsigned int& whi, unsigned int& wlo) {
    whi = packbf(v0, v1);
    float h0 = __uint_as_float(whi << 16);
    float h1 = __uint_as_float(whi & 0xffff0000u);
    wlo = packbf(v0 - h0, v1 - h1);
}

// tf32 m16n8k8
__device__ __forceinline__ void mma8(float* c, const unsigned int* a,
                                     unsigned int b0, unsigned int b1) {
    asm volatile(
        "mma.sync.aligned.m16n8k8.row.col.f32.tf32.tf32.f32 "
        "{%0,%1,%2,%3}, {%4,%5,%6,%7}, {%8,%9}, {%0,%1,%2,%3};"
        : "+f"(c[0]), "+f"(c[1]), "+f"(c[2]), "+f"(c[3])
        : "r"(a[0]), "r"(a[1]), "r"(a[2]), "r"(a[3]), "r"(b0), "r"(b1));
}
// bf16 m16n8k16
__device__ __forceinline__ void mma16(float* c, const unsigned int* a,
                                      unsigned int b0, unsigned int b1) {
    asm volatile(
        "mma.sync.aligned.m16n8k16.row.col.f32.bf16.bf16.f32 "
        "{%0,%1,%2,%3}, {%4,%5,%6,%7}, {%8,%9}, {%0,%1,%2,%3};"
        : "+f"(c[0]), "+f"(c[1]), "+f"(c[2]), "+f"(c[3])
        : "r"(a[0]), "r"(a[1]), "r"(a[2]), "r"(a[3]), "r"(b0), "r"(b1));
}

// ---------------------------------------------------------------------------
// Split-bf16 GEMM: C[M,Nc] = A[M,K] @ W[Nc,K]^T + bias  (~fp32 accurate)
// Block tile 128x128, 8 warps (4x2), warp tile 32x64, K-chunk 32 (2 k16 MMAs).
// smem word stride 20 -> conflict-free bf16x2 fragment reads. 40KB -> 2 CTA/SM.
// ---------------------------------------------------------------------------
#define GW      20
#define GPLANE  (128 * GW)
#define GEMM_SMEM (4 * GPLANE * 4)   // 40960 B

__global__ __launch_bounds__(256, 2) void gemm_bf16s(
    const float* __restrict__ A, const float* __restrict__ W,
    const float* __restrict__ bias, float* __restrict__ C,
    int M, int Nc, int K)
{
    extern __shared__ unsigned int gsm[];
    unsigned int* Ahw = gsm;
    unsigned int* Alw = gsm + GPLANE;
    unsigned int* Whw = gsm + 2 * GPLANE;
    unsigned int* Wlw = gsm + 3 * GPLANE;

    const int tid = threadIdx.x;
    const int warp = tid >> 5, lane = tid & 31;
    const int wm = warp >> 1, wn = warp & 1;
    const int g = lane >> 2, tig = lane & 3;
    const int m0 = blockIdx.x * 128, n0 = blockIdx.y * 128;

    float acc[2][8][4] = {};

    for (int k0 = 0; k0 < K; k0 += 32) {
        __syncthreads();   // previous-iteration fragment reads done
        #pragma unroll
        for (int i = 0; i < 4; i++) {
            int slot = tid + i * 256;        // 1024 float4 slots
            int r = slot >> 3;               // 8 float4 per 32-wide row
            int c4 = (slot & 7) * 4;
            float4 va = *(const float4*)&A[(size_t)(m0 + r) * K + k0 + c4];
            float4 vw = *(const float4*)&W[(size_t)(n0 + r) * K + k0 + c4];
            unsigned int h0, l0, h1, l1;
            split2(va.x, va.y, h0, l0);
            split2(va.z, va.w, h1, l1);
            *(uint2*)&Ahw[r * GW + (c4 >> 1)] = make_uint2(h0, h1);
            *(uint2*)&Alw[r * GW + (c4 >> 1)] = make_uint2(l0, l1);
            split2(vw.x, vw.y, h0, l0);
            split2(vw.z, vw.w, h1, l1);
            *(uint2*)&Whw[r * GW + (c4 >> 1)] = make_uint2(h0, h1);
            *(uint2*)&Wlw[r * GW + (c4 >> 1)] = make_uint2(l0, l1);
        }
        __syncthreads();

        #pragma unroll
        for (int s = 0; s < 2; s++) {
            unsigned int ah[2][4], al[2][4];
            const int cw = 8 * s + tig;
            #pragma unroll
            for (int mt = 0; mt < 2; mt++) {
                int row = wm * 32 + mt * 16;
                ah[mt][0] = Ahw[(row + g) * GW + cw];
                ah[mt][1] = Ahw[(row + g + 8) * GW + cw];
                ah[mt][2] = Ahw[(row + g) * GW + cw + 4];
                ah[mt][3] = Ahw[(row + g + 8) * GW + cw + 4];
                al[mt][0] = Alw[(row + g) * GW + cw];
                al[mt][1] = Alw[(row + g + 8) * GW + cw];
                al[mt][2] = Alw[(row + g) * GW + cw + 4];
                al[mt][3] = Alw[(row + g + 8) * GW + cw + 4];
            }
            #pragma unroll
            for (int nt = 0; nt < 8; nt++) {
                int nc = wn * 64 + nt * 8;
                unsigned int bh0 = Whw[(nc + g) * GW + cw];
                unsigned int bh1 = Whw[(nc + g) * GW + cw + 4];
                unsigned int bl0 = Wlw[(nc + g) * GW + cw];
                unsigned int bl1 = Wlw[(nc + g) * GW + cw + 4];
                #pragma unroll
                for (int mt = 0; mt < 2; mt++) {
                    mma16(acc[mt][nt], al[mt], bh0, bh1);
                    mma16(acc[mt][nt], ah[mt], bl0, bl1);
                    mma16(acc[mt][nt], ah[mt], bh0, bh1);
                }
            }
        }
    }

    #pragma unroll
    for (int mt = 0; mt < 2; mt++) {
        int r0 = m0 + wm * 32 + mt * 16 + g;
        #pragma unroll
        for (int nt = 0; nt < 8; nt++) {
            int c0 = n0 + wn * 64 + nt * 8 + 2 * tig;
            float b0v = bias[c0], b1v = bias[c0 + 1];
            *(float2*)&C[(size_t)r0 * Nc + c0] =
                make_float2(acc[mt][nt][0] + b0v, acc[mt][nt][1] + b1v);
            *(float2*)&C[(size_t)(r0 + 8) * Nc + c0] =
                make_float2(acc[mt][nt][2] + b0v, acc[mt][nt][3] + b1v);
        }
    }
}

// ---------------------------------------------------------------------------
// Causal flash attention, tf32 tensor cores, base-2 softmax.
// Block = 128 q-rows of one (b,h); 8 warps, each an m16 stripe.
// 2 CTAs/SM. K/V tiles of 64 keys in smem (stride 68, conflict-free frags).
// ---------------------------------------------------------------------------
#define ATT_SMEM ((2 * 64 * 68 + 128 * 68) * 4)   // 69632 B

__global__ __launch_bounds__(256, 2) void attn_tf32(
    const float* __restrict__ qkv, float* __restrict__ out)
{
    extern __shared__ unsigned int sm[];
    unsigned int (*Ks)[68] = (unsigned int(*)[68])(sm);
    unsigned int (*Vs)[68] = (unsigned int(*)[68])(sm + 64 * 68);
    unsigned int (*Ps)[68] = (unsigned int(*)[68])(sm + 2 * 64 * 68);

    const int iq = blockIdx.x, h = blockIdx.y, b = blockIdx.z;
    const int tid = threadIdx.x;
    const int w = tid >> 5, lane = tid & 31;
    const int g = lane >> 2, tig = lane & 3;
    const float* base = qkv + (size_t)b * NSEQ * QKV_COLS + h * HD;
    const int q0 = iq * 128;
    const int rw = 16 * w;                  // warp's local row base

    // Stage Q (tf32) into Ps (vectorized), then pull fragments into registers
    #pragma unroll
    for (int i = 0; i < 8; i++) {
        int slot = tid + i * 256;           // 2048 float4 slots (128x64)
        int r = slot >> 4, c = (slot & 15) * 4;
        float4 q = *(const float4*)(base + (size_t)(q0 + r) * QKV_COLS + c);
        *(uint4*)&Ps[r][c] = make_uint4(f2tf(q.x), f2tf(q.y), f2tf(q.z), f2tf(q.w));
    }
    __syncthreads();
    unsigned int qa[8][4];
    #pragma unroll
    for (int s = 0; s < 8; s++) {
        qa[s][0] = Ps[rw + g][8 * s + tig];
        qa[s][1] = Ps[rw + g + 8][8 * s + tig];
        qa[s][2] = Ps[rw + g][8 * s + tig + 4];
        qa[s][3] = Ps[rw + g + 8][8 * s + tig + 4];
    }

    float o[8][4] = {};
    float m0r = -1e30f, m1r = -1e30f, l0 = 0.f, l1 = 0.f;
    const int rowg0 = q0 + rw + g;
    const int rowg1 = rowg0 + 8;
    const int ktmax = 2 * iq + 1;
    const float SCALE2 = 0.18033688011112042f;   // 64^-0.5 * log2(e)

    for (int kt = 0; kt <= ktmax; kt++) {
        __syncthreads();   // prior Ks/Vs reads (and Q frag reads) complete
        #pragma unroll
        for (int i = 0; i < 4; i++) {
            int slot = tid + i * 256;       // 1024 float4 slots (64x64)
            int r = slot >> 4, c = (slot & 15) * 4;
            const float* kp = base + (size_t)(kt * 64 + r) * QKV_COLS + c;
            float4 kv = *(const float4*)(kp + EMBED);
            float4 vv = *(const float4*)(kp + 2 * EMBED);
            *(uint4*)&Ks[r][c] = make_uint4(f2tf(kv.x), f2tf(kv.y), f2tf(kv.z), f2tf(kv.w));
            *(uint4*)&Vs[r][c] = make_uint4(f2tf(vv.x), f2tf(vv.y), f2tf(vv.z), f2tf(vv.w));
        }
        __syncthreads();

        if (kt * 64 > q0 + rw + 15) continue;   // tile fully masked for warp

        // ---- S = Q @ K^T ----
        float sc[8][4] = {};
        #pragma unroll
        for (int s = 0; s < 8; s++) {
            #pragma unroll
            for (int nt = 0; nt < 8; nt++) {
                unsigned int b0 = Ks[8 * nt + g][8 * s + tig];
                unsigned int b1 = Ks[8 * nt + g][8 * s + tig + 4];
                mma8(sc[nt], qa[s], b0, b1);
            }
        }

        // scale (log2 domain) + causal mask (boundary tiles only)
        bool needmask = (kt * 64 + 63) > rowg0;
        #pragma unroll
        for (int nt = 0; nt < 8; nt++) {
            int c0 = kt * 64 + 8 * nt + 2 * tig;
            #pragma unroll
            for (int j = 0; j < 4; j++) sc[nt][j] *= SCALE2;
            if (needmask) {
                if (c0 > rowg0)     sc[nt][0] = -1e30f;
                if (c0 + 1 > rowg0) sc[nt][1] = -1e30f;
                if (c0 > rowg1)     sc[nt][2] = -1e30f;
                if (c0 + 1 > rowg1) sc[nt][3] = -1e30f;
            }
        }

        // ---- online softmax, base 2 (rows live in quads: shfl xor 1,2) ----
        float mx0 = -1e30f, mx1 = -1e30f;
        #pragma unroll
        for (int nt = 0; nt < 8; nt++) {
            mx0 = fmaxf(mx0, fmaxf(sc[nt][0], sc[nt][1]));
            mx1 = fmaxf(mx1, fmaxf(sc[nt][2], sc[nt][3]));
        }
        mx0 = fmaxf(mx0, __shfl_xor_sync(0xffffffffu, mx0, 1));
        mx0 = fmaxf(mx0, __shfl_xor_sync(0xffffffffu, mx0, 2));
        mx1 = fmaxf(mx1, __shfl_xor_sync(0xffffffffu, mx1, 1));
        mx1 = fmaxf(mx1, __shfl_xor_sync(0xffffffffu, mx1, 2));
        float mn0 = fmaxf(m0r, mx0), mn1 = fmaxf(m1r, mx1);
        float a0 = ex2(m0r - mn0), a1 = ex2(m1r - mn1);
        float s0 = 0.f, s1 = 0.f;
        #pragma unroll
        for (int nt = 0; nt < 8; nt++) {
            sc[nt][0] = ex2(sc[nt][0] - mn0);
            sc[nt][1] = ex2(sc[nt][1] - mn0);
            sc[nt][2] = ex2(sc[nt][2] - mn1);
            sc[nt][3] = ex2(sc[nt][3] - mn1);
            s0 += sc[nt][0] + sc[nt][1];
            s1 += sc[nt][2] + sc[nt][3];
        }
        s0 += __shfl_xor_sync(0xffffffffu, s0, 1);
        s0 += __shfl_xor_sync(0xffffffffu, s0, 2);
        s1 += __shfl_xor_sync(0xffffffffu, s1, 1);
        s1 += __shfl_xor_sync(0xffffffffu, s1, 2);
        l0 = l0 * a0 + s0;  l1 = l1 * a1 + s1;
        m0r = mn0;          m1r = mn1;
        #pragma unroll
        for (int nt = 0; nt < 8; nt++) {
            o[nt][0] *= a0; o[nt][1] *= a0;
            o[nt][2] *= a1; o[nt][3] *= a1;
        }

        // ---- P to warp-private smem rows, then O += P @ V ----
        #pragma unroll
        for (int nt = 0; nt < 8; nt++) {
            *(uint2*)&Ps[rw + g][8 * nt + 2 * tig] =
                make_uint2(f2tf(sc[nt][0]), f2tf(sc[nt][1]));
            *(uint2*)&Ps[rw + g + 8][8 * nt + 2 * tig] =
                make_uint2(f2tf(sc[nt][2]), f2tf(sc[nt][3]));
        }
        __syncwarp();
        #pragma unroll
        for (int s = 0; s < 8; s++) {
            unsigned int pa[4];
            pa[0] = Ps[rw + g][8 * s + tig];
            pa[1] = Ps[rw + g + 8][8 * s + tig];
            pa[2] = Ps[rw + g][8 * s + tig + 4];
            pa[3] = Ps[rw + g + 8][8 * s + tig + 4];
            #pragma unroll
            for (int nt = 0; nt < 8; nt++) {
                unsigned int b0 = Vs[8 * s + tig][8 * nt + g];
                unsigned int b1 = Vs[8 * s + tig + 4][8 * nt + g];
                mma8(o[nt], pa, b0, b1);
            }
        }
    }

    // epilogue
    float inv0 = 1.f / l0, inv1 = 1.f / l1;
    float* op0 = out + ((size_t)b * NSEQ + q0 + rw + g) * EMBED + h * HD;
    float* op1 = op0 + 8 * EMBED;
    #pragma unroll
    for (int nt = 0; nt < 8; nt++) {
        int c = 8 * nt + 2 * tig;
        *(float2*)&op0[c] = make_float2(o[nt][0] * inv0, o[nt][1] * inv0);
        *(float2*)&op1[c] = make_float2(o[nt][2] * inv1, o[nt][3] * inv1);
    }
}

// ---------------------------------------------------------------------------
extern "C" void kernel_launch(void* const* d_in, const int* in_sizes, int n_in,
                              void* d_out, int out_size)
{
    const float *x = nullptr, *qkv_w = nullptr, *qkv_b = nullptr;
    const float *out_w = nullptr, *out_b = nullptr;
    for (int i = 0; i < n_in; i++) {
        switch (in_sizes[i]) {
            case M_ROWS * EMBED:    x     = (const float*)d_in[i]; break;
            case EMBED * QKV_COLS:  qkv_w = (const float*)d_in[i]; break;
            case QKV_COLS:          qkv_b = (const float*)d_in[i]; break;
            case EMBED * EMBED:     out_w = (const float*)d_in[i]; break;
            case EMBED:             out_b = (const float*)d_in[i]; break;
            default: break;   // causal mask ignored (tril hardcoded)
        }
    }
    float* out = (float*)d_out;

    float *qkv_s, *att_s;
    cudaGetSymbolAddress((void**)&qkv_s, g_qkv);
    cudaGetSymbolAddress((void**)&att_s, g_att);

    static bool attr_done = false;
    if (!attr_done) {
        cudaFuncSetAttribute(attn_tf32,
                             cudaFuncAttributeMaxDynamicSharedMemorySize, ATT_SMEM);
        attr_done = true;
    }

    // 1) QKV projection: [8192,512] @ [1536,512]^T -> [8192,1536]
    gemm_bf16s<<<dim3(M_ROWS / 128, QKV_COLS / 128), 256, GEMM_SMEM>>>(
        x, qkv_w, qkv_b, qkv_s, M_ROWS, QKV_COLS, EMBED);

    // 2) Causal flash attention -> [8192,512]
    attn_tf32<<<dim3(NSEQ / 128, HEADS, BB), 256, ATT_SMEM>>>(qkv_s, att_s);

    // 3) Output projection: [8192,512] @ [512,512]^T -> d_out
    gemm_bf16s<<<dim3(M_ROWS / 128, EMBED / 128), 256, GEMM_SMEM>>>(
        att_s, out_w, out_b, out, M_ROWS, EMBED, EMBED);
}

// round 5
// speedup vs baseline: 4.6488x; 1.0369x over previous
#include <cuda_runtime.h>
#include <cuda_bf16.h>

#define EMBED   512
#define HEADS   8
#define HD      64
#define BB      2
#define NSEQ    4096
#define M_ROWS  (BB * NSEQ)          // 8192
#define QKV_COLS (3 * EMBED)         // 1536

// Scratch (allocation-free: __device__ globals)
__device__ float         g_qkv[(size_t)M_ROWS * QKV_COLS];   // tf32-rounded bits
__device__ __nv_bfloat16 g_xh[(size_t)M_ROWS * EMBED];
__device__ __nv_bfloat16 g_xl[(size_t)M_ROWS * EMBED];
__device__ __nv_bfloat16 g_wqh[(size_t)QKV_COLS * EMBED];
__device__ __nv_bfloat16 g_wql[(size_t)QKV_COLS * EMBED];
__device__ __nv_bfloat16 g_woh[(size_t)EMBED * EMBED];
__device__ __nv_bfloat16 g_wol[(size_t)EMBED * EMBED];
__device__ __nv_bfloat16 g_ah[(size_t)M_ROWS * EMBED];       // attn out hi
__device__ __nv_bfloat16 g_al[(size_t)M_ROWS * EMBED];       // attn out lo

// ---------------------------------------------------------------------------
// helpers
// ---------------------------------------------------------------------------
__device__ __forceinline__ unsigned int f2tf(float x) {
    unsigned int r;
    asm("cvt.rna.tf32.f32 %0, %1;" : "=r"(r) : "f"(x));
    return r;
}
__device__ __forceinline__ float ex2(float x) {
    float y;
    asm("ex2.approx.ftz.f32 %0, %1;" : "=f"(y) : "f"(x));
    return y;
}
__device__ __forceinline__ unsigned int packbf(float v0, float v1) {
    unsigned int r;
    asm("cvt.rn.bf16x2.f32 %0, %1, %2;" : "=r"(r) : "f"(v1), "f"(v0));
    return r;
}
__device__ __forceinline__ void split2(float v0, float v1,
                                       unsigned int& whi, unsigned int& wlo) {
    whi = packbf(v0, v1);
    float h0 = __uint_as_float(whi << 16);
    float h1 = __uint_as_float(whi & 0xffff0000u);
    wlo = packbf(v0 - h0, v1 - h1);
}
__device__ __forceinline__ void mma8(float* c, const unsigned int* a,
                                     unsigned int b0, unsigned int b1) {
    asm volatile(
        "mma.sync.aligned.m16n8k8.row.col.f32.tf32.tf32.f32 "
        "{%0,%1,%2,%3}, {%4,%5,%6,%7}, {%8,%9}, {%0,%1,%2,%3};"
        : "+f"(c[0]), "+f"(c[1]), "+f"(c[2]), "+f"(c[3])
        : "r"(a[0]), "r"(a[1]), "r"(a[2]), "r"(a[3]), "r"(b0), "r"(b1));
}
__device__ __forceinline__ void mma16(float* c, const unsigned int* a,
                                      unsigned int b0, unsigned int b1) {
    asm volatile(
        "mma.sync.aligned.m16n8k16.row.col.f32.bf16.bf16.f32 "
        "{%0,%1,%2,%3}, {%4,%5,%6,%7}, {%8,%9}, {%0,%1,%2,%3};"
        : "+f"(c[0]), "+f"(c[1]), "+f"(c[2]), "+f"(c[3])
        : "r"(a[0]), "r"(a[1]), "r"(a[2]), "r"(a[3]), "r"(b0), "r"(b1));
}
#define CP16(dst, src) \
    asm volatile("cp.async.cg.shared.global [%0], [%1], 16;" \
                 :: "r"(dst), "l"(src))
#define CP_COMMIT() asm volatile("cp.async.commit_group;")
#define CP_WAIT1()  asm volatile("cp.async.wait_group 1;")
#define CP_WAIT0()  asm volatile("cp.async.wait_group 0;")

// ---------------------------------------------------------------------------
// Pre-pass: split f32 -> bf16 hi/lo planes
// ---------------------------------------------------------------------------
__global__ __launch_bounds__(256) void split_kernel(
    const float* __restrict__ src, __nv_bfloat16* __restrict__ hi,
    __nv_bfloat16* __restrict__ lo, int n4)
{
    int i = blockIdx.x * 256 + threadIdx.x;
    if (i >= n4) return;
    float4 v = ((const float4*)src)[i];
    unsigned int h01, l01, h23, l23;
    split2(v.x, v.y, h01, l01);
    split2(v.z, v.w, h23, l23);
    ((uint2*)hi)[i] = make_uint2(h01, h23);
    ((uint2*)lo)[i] = make_uint2(l01, l23);
}

// ---------------------------------------------------------------------------
// Split-bf16 GEMM, cp.async double-buffered.
// C[M,Nc] = A @ W^T + bias, A/W given as bf16 hi/lo planes ([rows,K]).
// Block tile 128x128, 8 warps (4x2), warp 32x64, K-chunk 32 (2 k16 steps).
// smem: 2 buffers x 4 planes x 128 rows x 20 words = 81920 B -> 2 CTA/SM.
// CVT=1: output rounded to tf32 bits (feeds attention).
// ---------------------------------------------------------------------------
#define GW      20
#define GPL     (128 * GW)
#define GBUF    (4 * GPL)
#define GEMM_SMEM (2 * GBUF * 4)

template<int CVT>
__global__ __launch_bounds__(256, 2) void gemm_split(
    const __nv_bfloat16* __restrict__ Ahg, const __nv_bfloat16* __restrict__ Alg,
    const __nv_bfloat16* __restrict__ Whg, const __nv_bfloat16* __restrict__ Wlg,
    const float* __restrict__ bias, float* __restrict__ C, int Nc, int K)
{
    extern __shared__ unsigned int gsm[];
    const unsigned int sbase = (unsigned int)__cvta_generic_to_shared(gsm);

    const int tid = threadIdx.x;
    const int warp = tid >> 5, lane = tid & 31;
    const int wm = warp >> 1, wn = warp & 1;
    const int g = lane >> 2, tig = lane & 3;
    const int m0 = blockIdx.x * 128, n0 = blockIdx.y * 128;

    const __nv_bfloat16* planes[4] = {Ahg, Alg, Whg, Wlg};

    #define G_STAGE(k0, buf) do {                                             \
        _Pragma("unroll")                                                     \
        for (int i = 0; i < 8; i++) {                                         \
            const int plane = i >> 1;                                         \
            int idx2 = (i & 1) * 256 + tid;                                   \
            int r = idx2 >> 2, c = idx2 & 3;                                  \
            int row0 = (plane < 2) ? m0 : n0;                                 \
            const __nv_bfloat16* s = planes[plane] +                          \
                (size_t)(row0 + r) * K + (k0) + c * 8;                        \
            unsigned int d = sbase + ((buf) * GBUF + plane * GPL + r * GW) * 4 \
                             + c * 16;                                        \
            CP16(d, s);                                                       \
        }                                                                     \
    } while (0)

    float acc[2][8][4] = {};
    const int nIt = K / 32;

    G_STAGE(0, 0); CP_COMMIT();

    for (int it = 0; it < nIt; it++) {
        const int cur = it & 1;
        if (it + 1 < nIt) { G_STAGE((it + 1) * 32, cur ^ 1); CP_COMMIT(); CP_WAIT1(); }
        else              { CP_WAIT0(); }
        __syncthreads();

        const unsigned int* Ahw = gsm + cur * GBUF;
        const unsigned int* Alw = Ahw + GPL;
        const unsigned int* Whw = Ahw + 2 * GPL;
        const unsigned int* Wlw = Ahw + 3 * GPL;

        #pragma unroll
        for (int s = 0; s < 2; s++) {
            unsigned int ah[2][4], al[2][4];
            const int cw = 8 * s + tig;
            #pragma unroll
            for (int mt = 0; mt < 2; mt++) {
                int row = wm * 32 + mt * 16;
                ah[mt][0] = Ahw[(row + g) * GW + cw];
                ah[mt][1] = Ahw[(row + g + 8) * GW + cw];
                ah[mt][2] = Ahw[(row + g) * GW + cw + 4];
                ah[mt][3] = Ahw[(row + g + 8) * GW + cw + 4];
                al[mt][0] = Alw[(row + g) * GW + cw];
                al[mt][1] = Alw[(row + g + 8) * GW + cw];
                al[mt][2] = Alw[(row + g) * GW + cw + 4];
                al[mt][3] = Alw[(row + g + 8) * GW + cw + 4];
            }
            #pragma unroll
            for (int nt = 0; nt < 8; nt++) {
                int nc = wn * 64 + nt * 8;
                unsigned int bh0 = Whw[(nc + g) * GW + cw];
                unsigned int bh1 = Whw[(nc + g) * GW + cw + 4];
                unsigned int bl0 = Wlw[(nc + g) * GW + cw];
                unsigned int bl1 = Wlw[(nc + g) * GW + cw + 4];
                #pragma unroll
                for (int mt = 0; mt < 2; mt++) {
                    mma16(acc[mt][nt], al[mt], bh0, bh1);
                    mma16(acc[mt][nt], ah[mt], bl0, bl1);
                    mma16(acc[mt][nt], ah[mt], bh0, bh1);
                }
            }
        }
        __syncthreads();
    }

    #pragma unroll
    for (int mt = 0; mt < 2; mt++) {
        int r0 = m0 + wm * 32 + mt * 16 + g;
        #pragma unroll
        for (int nt = 0; nt < 8; nt++) {
            int c0 = n0 + wn * 64 + nt * 8 + 2 * tig;
            float b0v = bias[c0], b1v = bias[c0 + 1];
            float v0 = acc[mt][nt][0] + b0v, v1 = acc[mt][nt][1] + b1v;
            float v2 = acc[mt][nt][2] + b0v, v3 = acc[mt][nt][3] + b1v;
            if (CVT) {
                v0 = __uint_as_float(f2tf(v0)); v1 = __uint_as_float(f2tf(v1));
                v2 = __uint_as_float(f2tf(v2)); v3 = __uint_as_float(f2tf(v3));
            }
            *(float2*)&C[(size_t)r0 * Nc + c0] = make_float2(v0, v1);
            *(float2*)&C[(size_t)(r0 + 8) * Nc + c0] = make_float2(v2, v3);
        }
    }
}

// ---------------------------------------------------------------------------
// Causal flash attention, tf32 MMAs, base-2 softmax, cp.async double-buffered
// K/V tiles (inputs already tf32-rounded -> zero conversion at staging).
// Block = 128 q-rows of one (b,h); 8 warps = m16 stripes. 2 CTAs/SM.
// Output written as bf16 hi/lo split planes (feeds proj GEMM directly).
// ---------------------------------------------------------------------------
#define AW      68
#define KVW     (64 * AW)                       // words per K or V plane
#define ATT_SMEM ((4 * KVW + 128 * AW) * 4)     // 104448 B

__global__ __launch_bounds__(256, 2) void attn_tf32(void)
{
    extern __shared__ unsigned int sm[];
    const unsigned int sbase = (unsigned int)__cvta_generic_to_shared(sm);
    unsigned int (*Ps)[AW] = (unsigned int(*)[AW])(sm + 4 * KVW);

    const int iq = blockIdx.x, h = blockIdx.y, b = blockIdx.z;
    const int tid = threadIdx.x;
    const int w = tid >> 5, lane = tid & 31;
    const int g = lane >> 2, tig = lane & 3;
    const float* base = g_qkv + (size_t)b * NSEQ * QKV_COLS + h * HD;
    const int q0 = iq * 128;
    const int rw = 16 * w;

    #define A_STAGE(kt, buf) do {                                             \
        _Pragma("unroll")                                                     \
        for (int i = 0; i < 8; i++) {                                         \
            const int half = i >> 2;                                          \
            int idx2 = (i & 3) * 256 + tid;                                   \
            int r = idx2 >> 4, c = (idx2 & 15) * 4;                           \
            const float* s = base + (size_t)((kt) * 64 + r) * QKV_COLS        \
                             + (half ? 2 * EMBED : EMBED) + c;                \
            unsigned int d = sbase +                                          \
                (((buf) * 2 * KVW) + half * KVW + r * AW + c) * 4;            \
            CP16(d, s);                                                       \
        }                                                                     \
    } while (0)

    // prefetch tile 0 while staging Q
    A_STAGE(0, 0); CP_COMMIT();

    #pragma unroll
    for (int i = 0; i < 8; i++) {
        int slot = tid + i * 256;
        int r = slot >> 4, c = (slot & 15) * 4;
        *(uint4*)&Ps[r][c] =
            *(const uint4*)(base + (size_t)(q0 + r) * QKV_COLS + c);
    }
    __syncthreads();
    unsigned int qa[8][4];
    #pragma unroll
    for (int s = 0; s < 8; s++) {
        qa[s][0] = Ps[rw + g][8 * s + tig];
        qa[s][1] = Ps[rw + g + 8][8 * s + tig];
        qa[s][2] = Ps[rw + g][8 * s + tig + 4];
        qa[s][3] = Ps[rw + g + 8][8 * s + tig + 4];
    }

    float o[8][4] = {};
    float m0r = -1e30f, m1r = -1e30f, l0 = 0.f, l1 = 0.f;
    const int rowg0 = q0 + rw + g;
    const int rowg1 = rowg0 + 8;
    const int ktmax = 2 * iq + 1;
    const float SCALE2 = 0.18033688011112042f;   // 64^-0.5 * log2(e)

    for (int kt = 0; kt <= ktmax; kt++) {
        const int cur = kt & 1;
        if (kt < ktmax) { A_STAGE(kt + 1, cur ^ 1); CP_COMMIT(); CP_WAIT1(); }
        else            { CP_WAIT0(); }
        __syncthreads();

        if (kt * 64 <= q0 + rw + 15) {
            const unsigned int (*Ks)[AW] =
                (const unsigned int(*)[AW])(sm + cur * 2 * KVW);
            const unsigned int (*Vs)[AW] =
                (const unsigned int(*)[AW])(sm + cur * 2 * KVW + KVW);

            // ---- S = Q @ K^T ----
            float sc[8][4] = {};
            #pragma unroll
            for (int s = 0; s < 8; s++) {
                #pragma unroll
                for (int nt = 0; nt < 8; nt++) {
                    unsigned int b0 = Ks[8 * nt + g][8 * s + tig];
                    unsigned int b1 = Ks[8 * nt + g][8 * s + tig + 4];
                    mma8(sc[nt], qa[s], b0, b1);
                }
            }

            // scale (log2 domain) + causal mask
            bool needmask = (kt * 64 + 63) > rowg0;
            #pragma unroll
            for (int nt = 0; nt < 8; nt++) {
                int c0 = kt * 64 + 8 * nt + 2 * tig;
                #pragma unroll
                for (int j = 0; j < 4; j++) sc[nt][j] *= SCALE2;
                if (needmask) {
                    if (c0 > rowg0)     sc[nt][0] = -1e30f;
                    if (c0 + 1 > rowg0) sc[nt][1] = -1e30f;
                    if (c0 > rowg1)     sc[nt][2] = -1e30f;
                    if (c0 + 1 > rowg1) sc[nt][3] = -1e30f;
                }
            }

            // ---- online softmax (base 2) ----
            float mx0 = -1e30f, mx1 = -1e30f;
            #pragma unroll
            for (int nt = 0; nt < 8; nt++) {
                mx0 = fmaxf(mx0, fmaxf(sc[nt][0], sc[nt][1]));
                mx1 = fmaxf(mx1, fmaxf(sc[nt][2], sc[nt][3]));
            }
            mx0 = fmaxf(mx0, __shfl_xor_sync(0xffffffffu, mx0, 1));
            mx0 = fmaxf(mx0, __shfl_xor_sync(0xffffffffu, mx0, 2));
            mx1 = fmaxf(mx1, __shfl_xor_sync(0xffffffffu, mx1, 1));
            mx1 = fmaxf(mx1, __shfl_xor_sync(0xffffffffu, mx1, 2));
            float mn0 = fmaxf(m0r, mx0), mn1 = fmaxf(m1r, mx1);
            float a0 = ex2(m0r - mn0), a1 = ex2(m1r - mn1);
            float s0 = 0.f, s1 = 0.f;
            #pragma unroll
            for (int nt = 0; nt < 8; nt++) {
                sc[nt][0] = ex2(sc[nt][0] - mn0);
                sc[nt][1] = ex2(sc[nt][1] - mn0);
                sc[nt][2] = ex2(sc[nt][2] - mn1);
                sc[nt][3] = ex2(sc[nt][3] - mn1);
                s0 += sc[nt][0] + sc[nt][1];
                s1 += sc[nt][2] + sc[nt][3];
            }
            s0 += __shfl_xor_sync(0xffffffffu, s0, 1);
            s0 += __shfl_xor_sync(0xffffffffu, s0, 2);
            s1 += __shfl_xor_sync(0xffffffffu, s1, 1);
            s1 += __shfl_xor_sync(0xffffffffu, s1, 2);
            l0 = l0 * a0 + s0;  l1 = l1 * a1 + s1;
            m0r = mn0;          m1r = mn1;
            #pragma unroll
            for (int nt = 0; nt < 8; nt++) {
                o[nt][0] *= a0; o[nt][1] *= a0;
                o[nt][2] *= a1; o[nt][3] *= a1;
            }

            // ---- P -> warp-private smem rows, then O += P @ V ----
            #pragma unroll
            for (int nt = 0; nt < 8; nt++) {
                *(uint2*)&Ps[rw + g][8 * nt + 2 * tig] =
                    make_uint2(f2tf(sc[nt][0]), f2tf(sc[nt][1]));
                *(uint2*)&Ps[rw + g + 8][8 * nt + 2 * tig] =
                    make_uint2(f2tf(sc[nt][2]), f2tf(sc[nt][3]));
            }
            __syncwarp();
            #pragma unroll
            for (int s = 0; s < 8; s++) {
                unsigned int pa[4];
                pa[0] = Ps[rw + g][8 * s + tig];
                pa[1] = Ps[rw + g + 8][8 * s + tig];
                pa[2] = Ps[rw + g][8 * s + tig + 4];
                pa[3] = Ps[rw + g + 8][8 * s + tig + 4];
                #pragma unroll
                for (int nt = 0; nt < 8; nt++) {
                    unsigned int b0 = Vs[8 * s + tig][8 * nt + g];
                    unsigned int b1 = Vs[8 * s + tig + 4][8 * nt + g];
                    mma8(o[nt], pa, b0, b1);
                }
            }
        }
        __syncthreads();
    }

    // epilogue: normalize + write split bf16 planes
    float inv0 = 1.f / l0, inv1 = 1.f / l1;
    const size_t row0 = (size_t)b * NSEQ + q0 + rw + g;
    unsigned int* ah = (unsigned int*)g_ah;
    unsigned int* al = (unsigned int*)g_al;
    #pragma unroll
    for (int nt = 0; nt < 8; nt++) {
        int col = h * HD + 8 * nt + 2 * tig;
        unsigned int hw, lw;
        split2(o[nt][0] * inv0, o[nt][1] * inv0, hw, lw);
        ah[(row0 * EMBED + col) >> 1] = hw;
        al[(row0 * EMBED + col) >> 1] = lw;
        split2(o[nt][2] * inv1, o[nt][3] * inv1, hw, lw);
        ah[((row0 + 8) * EMBED + col) >> 1] = hw;
        al[((row0 + 8) * EMBED + col) >> 1] = lw;
    }
}

// ---------------------------------------------------------------------------
extern "C" void kernel_launch(void* const* d_in, const int* in_sizes, int n_in,
                              void* d_out, int out_size)
{
    const float *x = nullptr, *qkv_w = nullptr, *qkv_b = nullptr;
    const float *out_w = nullptr, *out_b = nullptr;
    for (int i = 0; i < n_in; i++) {
        switch (in_sizes[i]) {
            case M_ROWS * EMBED:    x     = (const float*)d_in[i]; break;
            case EMBED * QKV_COLS:  qkv_w = (const float*)d_in[i]; break;
            case QKV_COLS:          qkv_b = (const float*)d_in[i]; break;
            case EMBED * EMBED:     out_w = (const float*)d_in[i]; break;
            case EMBED:             out_b = (const float*)d_in[i]; break;
            default: break;   // causal mask ignored (tril hardcoded)
        }
    }
    float* out = (float*)d_out;

    float* qkv_s;
    __nv_bfloat16 *xh, *xl, *wqh, *wql, *woh, *wol, *ath, *atl;
    cudaGetSymbolAddress((void**)&qkv_s, g_qkv);
    cudaGetSymbolAddress((void**)&xh,  g_xh);
    cudaGetSymbolAddress((void**)&xl,  g_xl);
    cudaGetSymbolAddress((void**)&wqh, g_wqh);
    cudaGetSymbolAddress((void**)&wql, g_wql);
    cudaGetSymbolAddress((void**)&woh, g_woh);
    cudaGetSymbolAddress((void**)&wol, g_wol);
    cudaGetSymbolAddress((void**)&ath, g_ah);
    cudaGetSymbolAddress((void**)&atl, g_al);

    static bool attr_done = false;
    if (!attr_done) {
        cudaFuncSetAttribute(gemm_split<0>,
                             cudaFuncAttributeMaxDynamicSharedMemorySize, GEMM_SMEM);
        cudaFuncSetAttribute(gemm_split<1>,
                             cudaFuncAttributeMaxDynamicSharedMemorySize, GEMM_SMEM);
        cudaFuncSetAttribute(attn_tf32,
                             cudaFuncAttributeMaxDynamicSharedMemorySize, ATT_SMEM);
        attr_done = true;
    }

    // 0) split inputs into bf16 hi/lo planes
    split_kernel<<<(M_ROWS * EMBED / 4 + 255) / 256, 256>>>(x, xh, xl, M_ROWS * EMBED / 4);
    split_kernel<<<(QKV_COLS * EMBED / 4 + 255) / 256, 256>>>(qkv_w, wqh, wql, QKV_COLS * EMBED / 4);
    split_kernel<<<(EMBED * EMBED / 4 + 255) / 256, 256>>>(out_w, woh, wol, EMBED * EMBED / 4);

    // 1) QKV projection -> tf32-rounded g_qkv
    gemm_split<1><<<dim3(M_ROWS / 128, QKV_COLS / 128), 256, GEMM_SMEM>>>(
        xh, xl, wqh, wql, qkv_b, qkv_s, QKV_COLS, EMBED);

    // 2) Causal flash attention -> split planes g_ah/g_al
    attn_tf32<<<dim3(NSEQ / 128, HEADS, BB), 256, ATT_SMEM>>>();

    // 3) Output projection -> d_out (plain f32)
    gemm_split<0><<<dim3(M_ROWS / 128, EMBED / 128), 256, GEMM_SMEM>>>(
        ath, atl, woh, wol, out_b, out, EMBED, EMBED);
}

// round 8
// speedup vs baseline: 6.5521x; 1.4094x over previous
#include <cuda_runtime.h>
#include <cuda_bf16.h>

#define EMBED   512
#define HEADS   8
#define HD      64
#define BB      2
#define NSEQ    4096
#define M_ROWS  (BB * NSEQ)          // 8192
#define QKV_COLS (3 * EMBED)         // 1536

// Scratch (allocation-free: __device__ globals)
__device__ float         g_qkv[(size_t)M_ROWS * QKV_COLS];   // Q,K tf32-rounded
__device__ __align__(16) unsigned int g_vt[(size_t)BB * HEADS * HD * (NSEQ / 2)];
__device__ __nv_bfloat16 g_xh[(size_t)M_ROWS * EMBED];
__device__ __nv_bfloat16 g_xl[(size_t)M_ROWS * EMBED];
__device__ __nv_bfloat16 g_wqh[(size_t)QKV_COLS * EMBED];
__device__ __nv_bfloat16 g_wql[(size_t)QKV_COLS * EMBED];
__device__ __nv_bfloat16 g_woh[(size_t)EMBED * EMBED];
__device__ __nv_bfloat16 g_wol[(size_t)EMBED * EMBED];
__device__ __nv_bfloat16 g_ah[(size_t)M_ROWS * EMBED];       // attn out hi
__device__ __nv_bfloat16 g_al[(size_t)M_ROWS * EMBED];       // attn out lo

// ---------------------------------------------------------------------------
// helpers
// ---------------------------------------------------------------------------
__device__ __forceinline__ unsigned int f2tf(float x) {
    unsigned int r;
    asm("cvt.rna.tf32.f32 %0, %1;" : "=r"(r) : "f"(x));
    return r;
}
__device__ __forceinline__ float ex2(float x) {
    float y;
    asm("ex2.approx.ftz.f32 %0, %1;" : "=f"(y) : "f"(x));
    return y;
}
// pack two floats to bf16x2 (v0 -> low half, v1 -> high half)
__device__ __forceinline__ unsigned int packbf(float v0, float v1) {
    unsigned int r;
    asm("cvt.rn.bf16x2.f32 %0, %1, %2;" : "=r"(r) : "f"(v1), "f"(v0));
    return r;
}
// pack two floats to f16x2 (v0 -> low half, v1 -> high half)
__device__ __forceinline__ unsigned int packhf(float v0, float v1) {
    unsigned int r;
    asm("cvt.rn.f16x2.f32 %0, %1, %2;" : "=r"(r) : "f"(v1), "f"(v0));
    return r;
}
__device__ __forceinline__ void split2(float v0, float v1,
                                       unsigned int& whi, unsigned int& wlo) {
    whi = packbf(v0, v1);
    float h0 = __uint_as_float(whi << 16);
    float h1 = __uint_as_float(whi & 0xffff0000u);
    wlo = packbf(v0 - h0, v1 - h1);
}
__device__ __forceinline__ void mma8(float* c, const unsigned int* a,
                                     unsigned int b0, unsigned int b1) {
    asm volatile(
        "mma.sync.aligned.m16n8k8.row.col.f32.tf32.tf32.f32 "
        "{%0,%1,%2,%3}, {%4,%5,%6,%7}, {%8,%9}, {%0,%1,%2,%3};"
        : "+f"(c[0]), "+f"(c[1]), "+f"(c[2]), "+f"(c[3])
        : "r"(a[0]), "r"(a[1]), "r"(a[2]), "r"(a[3]), "r"(b0), "r"(b1));
}
__device__ __forceinline__ void mma16(float* c, const unsigned int* a,
                                      unsigned int b0, unsigned int b1) {
    asm volatile(
        "mma.sync.aligned.m16n8k16.row.col.f32.bf16.bf16.f32 "
        "{%0,%1,%2,%3}, {%4,%5,%6,%7}, {%8,%9}, {%0,%1,%2,%3};"
        : "+f"(c[0]), "+f"(c[1]), "+f"(c[2]), "+f"(c[3])
        : "r"(a[0]), "r"(a[1]), "r"(a[2]), "r"(a[3]), "r"(b0), "r"(b1));
}
// fp16 m16n8k16
__device__ __forceinline__ void mma16h(float* c, const unsigned int* a,
                                       unsigned int b0, unsigned int b1) {
    asm volatile(
        "mma.sync.aligned.m16n8k16.row.col.f32.f16.f16.f32 "
        "{%0,%1,%2,%3}, {%4,%5,%6,%7}, {%8,%9}, {%0,%1,%2,%3};"
        : "+f"(c[0]), "+f"(c[1]), "+f"(c[2]), "+f"(c[3])
        : "r"(a[0]), "r"(a[1]), "r"(a[2]), "r"(a[3]), "r"(b0), "r"(b1));
}
#define CP16(dst, src) \
    asm volatile("cp.async.cg.shared.global [%0], [%1], 16;" \
                 :: "r"(dst), "l"(src))
#define CP_COMMIT() asm volatile("cp.async.commit_group;")
#define CP_WAIT1()  asm volatile("cp.async.wait_group 1;")
#define CP_WAIT0()  asm volatile("cp.async.wait_group 0;")

// ---------------------------------------------------------------------------
// Pre-pass: split f32 -> bf16 hi/lo planes
// ---------------------------------------------------------------------------
__global__ __launch_bounds__(256) void split_kernel(
    const float* __restrict__ src, __nv_bfloat16* __restrict__ hi,
    __nv_bfloat16* __restrict__ lo, int n4)
{
    int i = blockIdx.x * 256 + threadIdx.x;
    if (i >= n4) return;
    float4 v = ((const float4*)src)[i];
    unsigned int h01, l01, h23, l23;
    split2(v.x, v.y, h01, l01);
    split2(v.z, v.w, h23, l23);
    ((uint2*)hi)[i] = make_uint2(h01, h23);
    ((uint2*)lo)[i] = make_uint2(l01, l23);
}

// ---------------------------------------------------------------------------
// Split-bf16 GEMM, cp.async double-buffered.
// CVT=1 (QKV): Q/K col-blocks -> tf32-rounded f32 into C (g_qkv);
//              V col-blocks (n0>=1024) -> f16x2 key-pair-packed g_vt ONLY.
// CVT=0 (proj): plain f32 out.
// ---------------------------------------------------------------------------
#define GW      20
#define GPL     (128 * GW)
#define GBUF    (4 * GPL)
#define GEMM_SMEM (2 * GBUF * 4)

template<int CVT>
__global__ __launch_bounds__(256, 2) void gemm_split(
    const __nv_bfloat16* __restrict__ Ahg, const __nv_bfloat16* __restrict__ Alg,
    const __nv_bfloat16* __restrict__ Whg, const __nv_bfloat16* __restrict__ Wlg,
    const float* __restrict__ bias, float* __restrict__ C, int Nc, int K)
{
    extern __shared__ unsigned int gsm[];
    const unsigned int sbase = (unsigned int)__cvta_generic_to_shared(gsm);

    const int tid = threadIdx.x;
    const int warp = tid >> 5, lane = tid & 31;
    const int wm = warp >> 1, wn = warp & 1;
    const int g = lane >> 2, tig = lane & 3;
    const int m0 = blockIdx.x * 128, n0 = blockIdx.y * 128;

    const __nv_bfloat16* planes[4] = {Ahg, Alg, Whg, Wlg};

    #define G_STAGE(k0, buf) do {                                             \
        _Pragma("unroll")                                                     \
        for (int i = 0; i < 8; i++) {                                         \
            const int plane = i >> 1;                                         \
            int idx2 = (i & 1) * 256 + tid;                                   \
            int r = idx2 >> 2, c = idx2 & 3;                                  \
            int row0 = (plane < 2) ? m0 : n0;                                 \
            const __nv_bfloat16* s = planes[plane] +                          \
                (size_t)(row0 + r) * K + (k0) + c * 8;                        \
            unsigned int d = sbase + ((buf) * GBUF + plane * GPL + r * GW) * 4 \
                             + c * 16;                                        \
            CP16(d, s);                                                       \
        }                                                                     \
    } while (0)

    float acc[2][8][4] = {};
    const int nIt = K / 32;

    G_STAGE(0, 0); CP_COMMIT();

    for (int it = 0; it < nIt; it++) {
        const int cur = it & 1;
        if (it + 1 < nIt) { G_STAGE((it + 1) * 32, cur ^ 1); CP_COMMIT(); CP_WAIT1(); }
        else              { CP_WAIT0(); }
        __syncthreads();

        const unsigned int* Ahw = gsm + cur * GBUF;
        const unsigned int* Alw = Ahw + GPL;
        const unsigned int* Whw = Ahw + 2 * GPL;
        const unsigned int* Wlw = Ahw + 3 * GPL;

        #pragma unroll
        for (int s = 0; s < 2; s++) {
            unsigned int ah[2][4], al[2][4];
            const int cw = 8 * s + tig;
            #pragma unroll
            for (int mt = 0; mt < 2; mt++) {
                int row = wm * 32 + mt * 16;
                ah[mt][0] = Ahw[(row + g) * GW + cw];
                ah[mt][1] = Ahw[(row + g + 8) * GW + cw];
                ah[mt][2] = Ahw[(row + g) * GW + cw + 4];
                ah[mt][3] = Ahw[(row + g + 8) * GW + cw + 4];
                al[mt][0] = Alw[(row + g) * GW + cw];
                al[mt][1] = Alw[(row + g + 8) * GW + cw];
                al[mt][2] = Alw[(row + g) * GW + cw + 4];
                al[mt][3] = Alw[(row + g + 8) * GW + cw + 4];
            }
            #pragma unroll
            for (int nt = 0; nt < 8; nt++) {
                int nc = wn * 64 + nt * 8;
                unsigned int bh0 = Whw[(nc + g) * GW + cw];
                unsigned int bh1 = Whw[(nc + g) * GW + cw + 4];
                unsigned int bl0 = Wlw[(nc + g) * GW + cw];
                unsigned int bl1 = Wlw[(nc + g) * GW + cw + 4];
                #pragma unroll
                for (int mt = 0; mt < 2; mt++) {
                    mma16(acc[mt][nt], al[mt], bh0, bh1);
                    mma16(acc[mt][nt], ah[mt], bl0, bl1);
                    mma16(acc[mt][nt], ah[mt], bh0, bh1);
                }
            }
        }
        __syncthreads();
    }

    if (CVT == 1 && n0 >= 2 * EMBED) {
        // V columns: write transposed f16x2 (key pairs) into g_vt only.
        #pragma unroll
        for (int mt = 0; mt < 2; mt++) {
            int r0 = m0 + wm * 32 + mt * 16 + g;
            int bidx = r0 >> 12, tok = r0 & 4095;
            #pragma unroll
            for (int nt = 0; nt < 8; nt++) {
                int c0 = n0 + wn * 64 + nt * 8 + 2 * tig;
                float b0v = bias[c0], b1v = bias[c0 + 1];
                float v0 = acc[mt][nt][0] + b0v, v1 = acc[mt][nt][1] + b1v;
                float v2 = acc[mt][nt][2] + b0v, v3 = acc[mt][nt][3] + b1v;
                float p0 = __shfl_xor_sync(0xffffffffu, v0, 4);
                float p1 = __shfl_xor_sync(0xffffffffu, v1, 4);
                float p2 = __shfl_xor_sync(0xffffffffu, v2, 4);
                float p3 = __shfl_xor_sync(0xffffffffu, v3, 4);
                if (!(g & 1)) {
                    int vcol = c0 - 2 * EMBED;
                    int hh = vcol >> 6, d = vcol & 63;
                    size_t basei = ((size_t)((bidx * HEADS + hh) * HD + d)) << 11;
                    size_t t2 = (size_t)(tok >> 1);
                    g_vt[basei + t2]            = packhf(v0, p0);
                    g_vt[basei + 2048 + t2]     = packhf(v1, p1);
                    g_vt[basei + t2 + 4]        = packhf(v2, p2);
                    g_vt[basei + 2048 + t2 + 4] = packhf(v3, p3);
                }
            }
        }
        return;
    }

    #pragma unroll
    for (int mt = 0; mt < 2; mt++) {
        int r0 = m0 + wm * 32 + mt * 16 + g;
        #pragma unroll
        for (int nt = 0; nt < 8; nt++) {
            int c0 = n0 + wn * 64 + nt * 8 + 2 * tig;
            float b0v = bias[c0], b1v = bias[c0 + 1];
            float v0 = acc[mt][nt][0] + b0v, v1 = acc[mt][nt][1] + b1v;
            float v2 = acc[mt][nt][2] + b0v, v3 = acc[mt][nt][3] + b1v;
            if (CVT) {
                v0 = __uint_as_float(f2tf(v0)); v1 = __uint_as_float(f2tf(v1));
                v2 = __uint_as_float(f2tf(v2)); v3 = __uint_as_float(f2tf(v3));
            }
            *(float2*)&C[(size_t)r0 * Nc + c0] = make_float2(v0, v1);
            *(float2*)&C[(size_t)(r0 + 8) * Nc + c0] = make_float2(v2, v3);
        }
    }
}

// ---------------------------------------------------------------------------
// Causal flash attention. S: tf32 MMA (K tf32-rounded in g_qkv).
// PV: fp16 m16n8k16 — P packed straight from S accumulators (no smem
// roundtrip), V staged pre-transposed f16x2 from g_vt (B-frag layout).
// Double-buffered cp.async K/V tiles; 2 CTAs/SM; heavy blocks launch first.
// ---------------------------------------------------------------------------
#define KPL  (64 * 68)               // K plane words
#define VPL  (64 * 36)               // V plane words (f16x2)
#define BUFW (KPL + VPL)
#define QOFF (2 * BUFW)
#define ATT_SMEM ((QOFF + 128 * 68) * 4)   // 88064 B

__global__ __launch_bounds__(256, 2) void attn_tf32(void)
{
    extern __shared__ unsigned int sm[];
    const unsigned int sbase = (unsigned int)__cvta_generic_to_shared(sm);
    unsigned int (*Qs)[68] = (unsigned int(*)[68])(sm + QOFF);

    const int iq = (gridDim.x - 1) - blockIdx.x;   // heavy blocks first
    const int h = blockIdx.y, b = blockIdx.z;
    const int tid = threadIdx.x;
    const int w = tid >> 5, lane = tid & 31;
    const int g = lane >> 2, tig = lane & 3;
    const float* qbase = g_qkv + (size_t)b * NSEQ * QKV_COLS + h * HD;
    const unsigned int* vtb = g_vt + (((size_t)(b * HEADS + h) * HD) << 11);
    const int q0 = iq * 128;
    const int rw = 16 * w;

    #define A_STAGE(kt, buf) do {                                             \
        _Pragma("unroll")                                                     \
        for (int i = 0; i < 4; i++) {   /* K tile: 64x64 f32 */               \
            int slot = i * 256 + tid;                                         \
            int r = slot >> 4, c4 = (slot & 15) * 4;                          \
            const float* s = qbase + (size_t)((kt) * 64 + r) * QKV_COLS       \
                             + EMBED + c4;                                    \
            unsigned int d = sbase + ((buf) * BUFW + r * 68 + c4) * 4;        \
            CP16(d, s);                                                       \
        }                                                                     \
        _Pragma("unroll")                                                     \
        for (int i = 0; i < 2; i++) {   /* V tile: 64d x 32 words f16x2 */    \
            int slot = i * 256 + tid;                                         \
            int dd = slot >> 3, w8 = slot & 7;                                \
            const unsigned int* s = vtb + dd * 2048 + (kt) * 32 + w8 * 4;     \
            unsigned int d = sbase + ((buf) * BUFW + KPL + dd * 36 + w8 * 4) * 4; \
            CP16(d, s);                                                       \
        }                                                                     \
    } while (0)

    // prefetch tile 0 while staging Q
    A_STAGE(0, 0); CP_COMMIT();

    #pragma unroll
    for (int i = 0; i < 8; i++) {
        int slot = tid + i * 256;
        int r = slot >> 4, c = (slot & 15) * 4;
        *(uint4*)&Qs[r][c] =
            *(const uint4*)(qbase + (size_t)(q0 + r) * QKV_COLS + c);
    }
    __syncthreads();
    unsigned int qa[8][4];
    #pragma unroll
    for (int s = 0; s < 8; s++) {
        qa[s][0] = Qs[rw + g][8 * s + tig];
        qa[s][1] = Qs[rw + g + 8][8 * s + tig];
        qa[s][2] = Qs[rw + g][8 * s + tig + 4];
        qa[s][3] = Qs[rw + g + 8][8 * s + tig + 4];
    }

    float o[8][4] = {};
    float m0r = -1e30f, m1r = -1e30f, l0 = 0.f, l1 = 0.f;
    const int rowg0 = q0 + rw + g;
    const int rowg1 = rowg0 + 8;
    const int ktmax = 2 * iq + 1;
    const float SCALE2 = 0.18033688011112042f;   // 64^-0.5 * log2(e)

    for (int kt = 0; kt <= ktmax; kt++) {
        const int cur = kt & 1;
        if (kt < ktmax) { A_STAGE(kt + 1, cur ^ 1); CP_COMMIT(); CP_WAIT1(); }
        else            { CP_WAIT0(); }
        __syncthreads();

        if (kt * 64 <= q0 + rw + 15) {
            const unsigned int (*Ks)[68] =
                (const unsigned int(*)[68])(sm + cur * BUFW);
            const unsigned int* Vt = sm + cur * BUFW + KPL;

            // ---- S = Q @ K^T (tf32) ----
            float sc[8][4] = {};
            #pragma unroll
            for (int s = 0; s < 8; s++) {
                #pragma unroll
                for (int nt = 0; nt < 8; nt++) {
                    unsigned int b0 = Ks[8 * nt + g][8 * s + tig];
                    unsigned int b1 = Ks[8 * nt + g][8 * s + tig + 4];
                    mma8(sc[nt], qa[s], b0, b1);
                }
            }

            // scale (log2 domain) + causal mask
            bool needmask = (kt * 64 + 63) > rowg0;
            #pragma unroll
            for (int nt = 0; nt < 8; nt++) {
                int c0 = kt * 64 + 8 * nt + 2 * tig;
                #pragma unroll
                for (int j = 0; j < 4; j++) sc[nt][j] *= SCALE2;
                if (needmask) {
                    if (c0 > rowg0)     sc[nt][0] = -1e30f;
                    if (c0 + 1 > rowg0) sc[nt][1] = -1e30f;
                    if (c0 > rowg1)     sc[nt][2] = -1e30f;
                    if (c0 + 1 > rowg1) sc[nt][3] = -1e30f;
                }
            }

            // ---- online softmax (base 2) ----
            float mx0 = -1e30f, mx1 = -1e30f;
            #pragma unroll
            for (int nt = 0; nt < 8; nt++) {
                mx0 = fmaxf(mx0, fmaxf(sc[nt][0], sc[nt][1]));
                mx1 = fmaxf(mx1, fmaxf(sc[nt][2], sc[nt][3]));
            }
            mx0 = fmaxf(mx0, __shfl_xor_sync(0xffffffffu, mx0, 1));
            mx0 = fmaxf(mx0, __shfl_xor_sync(0xffffffffu, mx0, 2));
            mx1 = fmaxf(mx1, __shfl_xor_sync(0xffffffffu, mx1, 1));
            mx1 = fmaxf(mx1, __shfl_xor_sync(0xffffffffu, mx1, 2));
            float mn0 = fmaxf(m0r, mx0), mn1 = fmaxf(m1r, mx1);
            float a0 = ex2(m0r - mn0), a1 = ex2(m1r - mn1);
            float s0 = 0.f, s1 = 0.f;
            #pragma unroll
            for (int nt = 0; nt < 8; nt++) {
                sc[nt][0] = ex2(sc[nt][0] - mn0);
                sc[nt][1] = ex2(sc[nt][1] - mn0);
                sc[nt][2] = ex2(sc[nt][2] - mn1);
                sc[nt][3] = ex2(sc[nt][3] - mn1);
                s0 += sc[nt][0] + sc[nt][1];
                s1 += sc[nt][2] + sc[nt][3];
            }
            s0 += __shfl_xor_sync(0xffffffffu, s0, 1);
            s0 += __shfl_xor_sync(0xffffffffu, s0, 2);
            s1 += __shfl_xor_sync(0xffffffffu, s1, 1);
            s1 += __shfl_xor_sync(0xffffffffu, s1, 2);
            l0 = l0 * a0 + s0;  l1 = l1 * a1 + s1;
            m0r = mn0;          m1r = mn1;
            #pragma unroll
            for (int nt = 0; nt < 8; nt++) {
                o[nt][0] *= a0; o[nt][1] *= a0;
                o[nt][2] *= a1; o[nt][3] *= a1;
            }

            // ---- O += P @ V : fp16 k16, P packed straight from accums ----
            #pragma unroll
            for (int s = 0; s < 4; s++) {
                unsigned int pa[4];
                pa[0] = packhf(sc[2 * s][0],     sc[2 * s][1]);
                pa[1] = packhf(sc[2 * s][2],     sc[2 * s][3]);
                pa[2] = packhf(sc[2 * s + 1][0], sc[2 * s + 1][1]);
                pa[3] = packhf(sc[2 * s + 1][2], sc[2 * s + 1][3]);
                #pragma unroll
                for (int nt = 0; nt < 8; nt++) {
                    unsigned int b0 = Vt[(8 * nt + g) * 36 + 8 * s + tig];
                    unsigned int b1 = Vt[(8 * nt + g) * 36 + 8 * s + 4 + tig];
                    mma16h(o[nt], pa, b0, b1);
                }
            }
        }
        __syncthreads();
    }

    // epilogue: normalize + write split bf16 planes (feeds proj GEMM)
    float inv0 = 1.f / l0, inv1 = 1.f / l1;
    const size_t row0 = (size_t)b * NSEQ + q0 + rw + g;
    unsigned int* ah = (unsigned int*)g_ah;
    unsigned int* al = (unsigned int*)g_al;
    #pragma unroll
    for (int nt = 0; nt < 8; nt++) {
        int col = h * HD + 8 * nt + 2 * tig;
        unsigned int hw, lw;
        split2(o[nt][0] * inv0, o[nt][1] * inv0, hw, lw);
        ah[(row0 * EMBED + col) >> 1] = hw;
        al[(row0 * EMBED + col) >> 1] = lw;
        split2(o[nt][2] * inv1, o[nt][3] * inv1, hw, lw);
        ah[((row0 + 8) * EMBED + col) >> 1] = hw;
        al[((row0 + 8) * EMBED + col) >> 1] = lw;
    }
}

// ---------------------------------------------------------------------------
extern "C" void kernel_launch(void* const* d_in, const int* in_sizes, int n_in,
                              void* d_out, int out_size)
{
    const float *x = nullptr, *qkv_w = nullptr, *qkv_b = nullptr;
    const float *out_w = nullptr, *out_b = nullptr;
    for (int i = 0; i < n_in; i++) {
        switch (in_sizes[i]) {
            case M_ROWS * EMBED:    x     = (const float*)d_in[i]; break;
            case EMBED * QKV_COLS:  qkv_w = (const float*)d_in[i]; break;
            case QKV_COLS:          qkv_b = (const float*)d_in[i]; break;
            case EMBED * EMBED:     out_w = (const float*)d_in[i]; break;
            case EMBED:             out_b = (const float*)d_in[i]; break;
            default: break;   // causal mask ignored (tril hardcoded)
        }
    }
    float* out = (float*)d_out;

    float* qkv_s;
    __nv_bfloat16 *xh, *xl, *wqh, *wql, *woh, *wol, *ath, *atl;
    cudaGetSymbolAddress((void**)&qkv_s, g_qkv);
    cudaGetSymbolAddress((void**)&xh,  g_xh);
    cudaGetSymbolAddress((void**)&xl,  g_xl);
    cudaGetSymbolAddress((void**)&wqh, g_wqh);
    cudaGetSymbolAddress((void**)&wql, g_wql);
    cudaGetSymbolAddress((void**)&woh, g_woh);
    cudaGetSymbolAddress((void**)&wol, g_wol);
    cudaGetSymbolAddress((void**)&ath, g_ah);
    cudaGetSymbolAddress((void**)&atl, g_al);

    static bool attr_done = false;
    if (!attr_done) {
        cudaFuncSetAttribute(gemm_split<0>,
                             cudaFuncAttributeMaxDynamicSharedMemorySize, GEMM_SMEM);
        cudaFuncSetAttribute(gemm_split<1>,
                             cudaFuncAttributeMaxDynamicSharedMemorySize, GEMM_SMEM);
        cudaFuncSetAttribute(attn_tf32,
                             cudaFuncAttributeMaxDynamicSharedMemorySize, ATT_SMEM);
        attr_done = true;
    }

    // 0) split inputs into bf16 hi/lo planes
    split_kernel<<<(M_ROWS * EMBED / 4 + 255) / 256, 256>>>(x, xh, xl, M_ROWS * EMBED / 4);
    split_kernel<<<(QKV_COLS * EMBED / 4 + 255) / 256, 256>>>(qkv_w, wqh, wql, QKV_COLS * EMBED / 4);
    split_kernel<<<(EMBED * EMBED / 4 + 255) / 256, 256>>>(out_w, woh, wol, EMBED * EMBED / 4);

    // 1) QKV projection -> Q,K tf32-rounded g_qkv; V transposed f16x2 g_vt
    gemm_split<1><<<dim3(M_ROWS / 128, QKV_COLS / 128), 256, GEMM_SMEM>>>(
        xh, xl, wqh, wql, qkv_b, qkv_s, QKV_COLS, EMBED);

    // 2) Causal flash attention -> split planes g_ah/g_al
    attn_tf32<<<dim3(NSEQ / 128, HEADS, BB), 256, ATT_SMEM>>>();

    // 3) Output projection -> d_out (plain f32)
    gemm_split<0><<<dim3(M_ROWS / 128, EMBED / 128), 256, GEMM_SMEM>>>(
        ath, atl, woh, wol, out_b, out, EMBED, EMBED);
}

// round 12
// speedup vs baseline: 6.7427x; 1.0291x over previous
#include <cuda_runtime.h>
#include <cuda_bf16.h>

#define EMBED   512
#define HEADS   8
#define HD      64
#define BB      2
#define NSEQ    4096
#define M_ROWS  (BB * NSEQ)          // 8192
#define QKV_COLS (3 * EMBED)         // 1536
#define KW      (EMBED / 2)          // 256 words per row (f16x2)

// Scratch (allocation-free: __device__ globals) — all packed f16x2 words
__device__ __align__(16) unsigned int g_xp [(size_t)M_ROWS * KW];
__device__ __align__(16) unsigned int g_wqp[(size_t)QKV_COLS * KW];
__device__ __align__(16) unsigned int g_wop[(size_t)EMBED * KW];
__device__ __align__(16) unsigned int g_qp [(size_t)M_ROWS * KW];   // Q  [tok][d-pair]
__device__ __align__(16) unsigned int g_kp [(size_t)M_ROWS * KW];   // K  [tok][d-pair]
__device__ __align__(16) unsigned int g_vt [(size_t)BB * HEADS * HD * (NSEQ / 2)]; // V^T [d][tok-pair]
__device__ __align__(16) unsigned int g_op [(size_t)M_ROWS * KW];   // attn O [tok][d-pair]

// ---------------------------------------------------------------------------
// helpers
// ---------------------------------------------------------------------------
__device__ __forceinline__ float ex2(float x) {
    float y;
    asm("ex2.approx.ftz.f32 %0, %1;" : "=f"(y) : "f"(x));
    return y;
}
// pack two floats to f16x2 (v0 -> low half, v1 -> high half)
__device__ __forceinline__ unsigned int packhf(float v0, float v1) {
    unsigned int r;
    asm("cvt.rn.f16x2.f32 %0, %1, %2;" : "=r"(r) : "f"(v1), "f"(v0));
    return r;
}
// fp16 m16n8k16, f32 accumulate
__device__ __forceinline__ void mma16h(float* c, const unsigned int* a,
                                       unsigned int b0, unsigned int b1) {
    asm volatile(
        "mma.sync.aligned.m16n8k16.row.col.f32.f16.f16.f32 "
        "{%0,%1,%2,%3}, {%4,%5,%6,%7}, {%8,%9}, {%0,%1,%2,%3};"
        : "+f"(c[0]), "+f"(c[1]), "+f"(c[2]), "+f"(c[3])
        : "r"(a[0]), "r"(a[1]), "r"(a[2]), "r"(a[3]), "r"(b0), "r"(b1));
}
#define CP16(dst, src) \
    asm volatile("cp.async.cg.shared.global [%0], [%1], 16;" \
                 :: "r"(dst), "l"(src))
#define CP_COMMIT() asm volatile("cp.async.commit_group;")
#define CP_WAIT1()  asm volatile("cp.async.wait_group 1;")
#define CP_WAIT0()  asm volatile("cp.async.wait_group 0;")

// ---------------------------------------------------------------------------
// Pre-pass: pack f32 -> f16x2 words (pairs along contiguous K dim)
// ---------------------------------------------------------------------------
__global__ __launch_bounds__(256) void pack_f16(
    const float* __restrict__ src, unsigned int* __restrict__ dst, int n4)
{
    int i = blockIdx.x * 256 + threadIdx.x;
    if (i >= n4) return;
    float4 v = ((const float4*)src)[i];
    ((uint2*)dst)[i] = make_uint2(packhf(v.x, v.y), packhf(v.z, v.w));
}

// ---------------------------------------------------------------------------
// fp16 GEMM, cp.async double-buffered: C[M,Nc] = A @ W^T + bias.
// A, W packed f16x2 [rows][Kw words]. Block tile 128x128, 8 warps (4x2),
// warp 32x64, K-chunk 32 elements (2 k16 steps). Row pad 20 words.
// OUT=0: f32 C out (proj). OUT=1: QKV routing — Q,K f16x2 d-pairs to
// g_qp/g_kp; V transposed f16x2 key-pairs to g_vt.
// ---------------------------------------------------------------------------
#define GW2   20
#define GPL2  (128 * GW2)
#define GBUF2 (2 * GPL2)
#define GEMM_SMEM (2 * GBUF2 * 4)    // 40960 B

template<int OUT>
__global__ __launch_bounds__(256, 2) void gemm_f16(
    const unsigned int* __restrict__ Ap, const unsigned int* __restrict__ Wp,
    const float* __restrict__ bias, float* __restrict__ C, int Nc, int Kw)
{
    extern __shared__ unsigned int gsm[];
    const unsigned int sbase = (unsigned int)__cvta_generic_to_shared(gsm);

    const int tid = threadIdx.x;
    const int warp = tid >> 5, lane = tid & 31;
    const int wm = warp >> 1, wn = warp & 1;
    const int g = lane >> 2, tig = lane & 3;
    const int m0 = blockIdx.x * 128, n0 = blockIdx.y * 128;

    #define G_STAGE(kw0, buf) do {                                            \
        _Pragma("unroll")                                                     \
        for (int i = 0; i < 4; i++) {                                         \
            const int plane = i >> 1;                                         \
            int idx = (i & 1) * 256 + tid;                                    \
            int r = idx >> 2, c4 = (idx & 3) * 4;                             \
            const unsigned int* s = (plane ? Wp : Ap) +                       \
                (size_t)(((plane ? n0 : m0) + r)) * Kw + (kw0) + c4;          \
            unsigned int d = sbase +                                          \
                ((buf) * GBUF2 + plane * GPL2 + r * GW2 + c4) * 4;            \
            CP16(d, s);                                                       \
        }                                                                     \
    } while (0)

    float acc[2][8][4] = {};
    const int nIt = Kw / 16;          // 16 words = 32 elements per chunk

    G_STAGE(0, 0); CP_COMMIT();

    for (int it = 0; it < nIt; it++) {
        const int cur = it & 1;
        if (it + 1 < nIt) { G_STAGE((it + 1) * 16, cur ^ 1); CP_COMMIT(); CP_WAIT1(); }
        else              { CP_WAIT0(); }
        __syncthreads();

        const unsigned int* Aw = gsm + cur * GBUF2;
        const unsigned int* Ww = Aw + GPL2;

        #pragma unroll
        for (int s = 0; s < 2; s++) {
            const int cw = 8 * s + tig;
            unsigned int ah[2][4];
            #pragma unroll
            for (int mt = 0; mt < 2; mt++) {
                int row = wm * 32 + mt * 16;
                ah[mt][0] = Aw[(row + g) * GW2 + cw];
                ah[mt][1] = Aw[(row + g + 8) * GW2 + cw];
                ah[mt][2] = Aw[(row + g) * GW2 + cw + 4];
                ah[mt][3] = Aw[(row + g + 8) * GW2 + cw + 4];
            }
            #pragma unroll
            for (int nt = 0; nt < 8; nt++) {
                int nc = wn * 64 + nt * 8;
                unsigned int b0 = Ww[(nc + g) * GW2 + cw];
                unsigned int b1 = Ww[(nc + g) * GW2 + cw + 4];
                #pragma unroll
                for (int mt = 0; mt < 2; mt++)
                    mma16h(acc[mt][nt], ah[mt], b0, b1);
            }
        }
        __syncthreads();
    }

    if (OUT == 1) {
        #pragma unroll
        for (int mt = 0; mt < 2; mt++) {
            int r0 = m0 + wm * 32 + mt * 16 + g;
            #pragma unroll
            for (int nt = 0; nt < 8; nt++) {
                int c0 = n0 + wn * 64 + nt * 8 + 2 * tig;
                float b0v = bias[c0], b1v = bias[c0 + 1];
                float v0 = acc[mt][nt][0] + b0v, v1 = acc[mt][nt][1] + b1v;
                float v2 = acc[mt][nt][2] + b0v, v3 = acc[mt][nt][3] + b1v;
                if (c0 < 2 * EMBED) {
                    // Q or K: pack d-pairs in place
                    unsigned int* dst = (c0 < EMBED) ? g_qp : g_kp;
                    int cc = (c0 & (EMBED - 1)) >> 1;
                    dst[(size_t)r0 * KW + cc]       = packhf(v0, v1);
                    dst[(size_t)(r0 + 8) * KW + cc] = packhf(v2, v3);
                } else {
                    // V: transpose to [d][token-pair] f16x2
                    float p0 = __shfl_xor_sync(0xffffffffu, v0, 4);
                    float p1 = __shfl_xor_sync(0xffffffffu, v1, 4);
                    float p2 = __shfl_xor_sync(0xffffffffu, v2, 4);
                    float p3 = __shfl_xor_sync(0xffffffffu, v3, 4);
                    if (!(g & 1)) {
                        int bidx = r0 >> 12, tok = r0 & 4095;
                        int vcol = c0 - 2 * EMBED;
                        int hh = vcol >> 6, d = vcol & 63;
                        size_t basei = ((size_t)((bidx * HEADS + hh) * HD + d)) << 11;
                        size_t t2 = (size_t)(tok >> 1);
                        g_vt[basei + t2]            = packhf(v0, p0);
                        g_vt[basei + 2048 + t2]     = packhf(v1, p1);
                        g_vt[basei + t2 + 4]        = packhf(v2, p2);
                        g_vt[basei + 2048 + t2 + 4] = packhf(v3, p3);
                    }
                }
            }
        }
        return;
    }

    #pragma unroll
    for (int mt = 0; mt < 2; mt++) {
        int r0 = m0 + wm * 32 + mt * 16 + g;
        #pragma unroll
        for (int nt = 0; nt < 8; nt++) {
            int c0 = n0 + wn * 64 + nt * 8 + 2 * tig;
            float b0v = bias[c0], b1v = bias[c0 + 1];
            *(float2*)&C[(size_t)r0 * Nc + c0] =
                make_float2(acc[mt][nt][0] + b0v, acc[mt][nt][1] + b1v);
            *(float2*)&C[(size_t)(r0 + 8) * Nc + c0] =
                make_float2(acc[mt][nt][2] + b0v, acc[mt][nt][3] + b1v);
        }
    }
}

// ---------------------------------------------------------------------------
// Causal flash attention — all fp16 tensor ops, f32 accumulate.
// S: fp16 k16 (Q,K pre-packed f16x2 d-pairs). PV: fp16 k16, P packed
// straight from S accumulators, V pre-transposed f16x2 (B-frag layout).
// Double-buffered cp.async; 2 CTAs/SM; heavy q-blocks launch first.
// ---------------------------------------------------------------------------
#define AW2   36
#define KPL2  (64 * AW2)             // K plane words per tile
#define VPL2  (64 * AW2)
#define BUFW2 (KPL2 + VPL2)
#define QOFF2 (2 * BUFW2)
#define ATT_SMEM ((QOFF2 + 128 * AW2) * 4)   // 55296 B

__global__ __launch_bounds__(256, 2) void attn_f16(void)
{
    extern __shared__ unsigned int sm[];
    const unsigned int sbase = (unsigned int)__cvta_generic_to_shared(sm);
    unsigned int (*Qs)[AW2] = (unsigned int(*)[AW2])(sm + QOFF2);

    const int iq = (gridDim.x - 1) - blockIdx.x;   // heavy blocks first
    const int h = blockIdx.y, b = blockIdx.z;
    const int tid = threadIdx.x;
    const int w = tid >> 5, lane = tid & 31;
    const int g = lane >> 2, tig = lane & 3;
    const unsigned int* qbase = g_qp + ((size_t)b * NSEQ) * KW + h * (HD / 2);
    const unsigned int* kbase = g_kp + ((size_t)b * NSEQ) * KW + h * (HD / 2);
    const unsigned int* vtb = g_vt + (((size_t)(b * HEADS + h) * HD) << 11);
    const int q0 = iq * 128;
    const int rw = 16 * w;

    #define A_STAGE(kt, buf) do {                                             \
        _Pragma("unroll")                                                     \
        for (int i = 0; i < 2; i++) {   /* K tile: 64 keys x 32 words */      \
            int slot = i * 256 + tid;                                         \
            int r = slot >> 3, w8 = slot & 7;                                 \
            const unsigned int* s = kbase + (size_t)((kt) * 64 + r) * KW      \
                                    + w8 * 4;                                 \
            unsigned int d = sbase + ((buf) * BUFW2 + r * AW2 + w8 * 4) * 4;  \
            CP16(d, s);                                                       \
        }                                                                     \
        _Pragma("unroll")                                                     \
        for (int i = 0; i < 2; i++) {   /* V tile: 64 d x 32 words */         \
            int slot = i * 256 + tid;                                         \
            int dd = slot >> 3, w8 = slot & 7;                                \
            const unsigned int* s = vtb + dd * 2048 + (kt) * 32 + w8 * 4;     \
            unsigned int d = sbase +                                          \
                ((buf) * BUFW2 + KPL2 + dd * AW2 + w8 * 4) * 4;               \
            CP16(d, s);                                                       \
        }                                                                     \
    } while (0)

    // prefetch tile 0 + Q tile
    A_STAGE(0, 0);
    #pragma unroll
    for (int i = 0; i < 4; i++) {       // Q: 128 rows x 32 words
        int slot = i * 256 + tid;
        int r = slot >> 3, w8 = slot & 7;
        const unsigned int* s = qbase + (size_t)(q0 + r) * KW + w8 * 4;
        unsigned int d = sbase + (QOFF2 + r * AW2 + w8 * 4) * 4;
        CP16(d, s);
    }
    CP_COMMIT();
    CP_WAIT0();
    __syncthreads();

    unsigned int qa[4][4];
    #pragma unroll
    for (int s = 0; s < 4; s++) {
        qa[s][0] = Qs[rw + g][8 * s + tig];
        qa[s][1] = Qs[rw + g + 8][8 * s + tig];
        qa[s][2] = Qs[rw + g][8 * s + tig + 4];
        qa[s][3] = Qs[rw + g + 8][8 * s + tig + 4];
    }

    float o[8][4] = {};
    float m0r = -1e30f, m1r = -1e30f, l0 = 0.f, l1 = 0.f;
    const int rowg0 = q0 + rw + g;
    const int rowg1 = rowg0 + 8;
    const int ktmax = 2 * iq + 1;
    const float SCALE2 = 0.18033688011112042f;   // 64^-0.5 * log2(e)

    for (int kt = 0; kt <= ktmax; kt++) {
        const int cur = kt & 1;
        if (kt < ktmax) { A_STAGE(kt + 1, cur ^ 1); CP_COMMIT(); CP_WAIT1(); }
        else            { CP_WAIT0(); }
        __syncthreads();

        if (kt * 64 <= q0 + rw + 15) {
            const unsigned int* Ksw = sm + cur * BUFW2;
            const unsigned int* Vt  = sm + cur * BUFW2 + KPL2;

            // ---- S = Q @ K^T (fp16 k16) ----
            float sc[8][4] = {};
            #pragma unroll
            for (int s = 0; s < 4; s++) {
                #pragma unroll
                for (int nt = 0; nt < 8; nt++) {
                    unsigned int b0 = Ksw[(8 * nt + g) * AW2 + 8 * s + tig];
                    unsigned int b1 = Ksw[(8 * nt + g) * AW2 + 8 * s + 4 + tig];
                    mma16h(sc[nt], qa[s], b0, b1);
                }
            }

            // scale (log2 domain) + causal mask (boundary tiles only)
            bool needmask = (kt * 64 + 63) > rowg0;
            #pragma unroll
            for (int nt = 0; nt < 8; nt++) {
                int c0 = kt * 64 + 8 * nt + 2 * tig;
                #pragma unroll
                for (int j = 0; j < 4; j++) sc[nt][j] *= SCALE2;
                if (needmask) {
                    if (c0 > rowg0)     sc[nt][0] = -1e30f;
                    if (c0 + 1 > rowg0) sc[nt][1] = -1e30f;
                    if (c0 > rowg1)     sc[nt][2] = -1e30f;
                    if (c0 + 1 > rowg1) sc[nt][3] = -1e30f;
                }
            }

            // ---- online softmax (base 2; rows in quads: shfl xor 1,2) ----
            float mx0 = -1e30f, mx1 = -1e30f;
            #pragma unroll
            for (int nt = 0; nt < 8; nt++) {
                mx0 = fmaxf(mx0, fmaxf(sc[nt][0], sc[nt][1]));
                mx1 = fmaxf(mx1, fmaxf(sc[nt][2], sc[nt][3]));
            }
            mx0 = fmaxf(mx0, __shfl_xor_sync(0xffffffffu, mx0, 1));
            mx0 = fmaxf(mx0, __shfl_xor_sync(0xffffffffu, mx0, 2));
            mx1 = fmaxf(mx1, __shfl_xor_sync(0xffffffffu, mx1, 1));
            mx1 = fmaxf(mx1, __shfl_xor_sync(0xffffffffu, mx1, 2));
            float mn0 = fmaxf(m0r, mx0), mn1 = fmaxf(m1r, mx1);
            float a0 = ex2(m0r - mn0), a1 = ex2(m1r - mn1);
            float s0 = 0.f, s1 = 0.f;
            #pragma unroll
            for (int nt = 0; nt < 8; nt++) {
                sc[nt][0] = ex2(sc[nt][0] - mn0);
                sc[nt][1] = ex2(sc[nt][1] - mn0);
                sc[nt][2] = ex2(sc[nt][2] - mn1);
                sc[nt][3] = ex2(sc[nt][3] - mn1);
                s0 += sc[nt][0] + sc[nt][1];
                s1 += sc[nt][2] + sc[nt][3];
            }
            s0 += __shfl_xor_sync(0xffffffffu, s0, 1);
            s0 += __shfl_xor_sync(0xffffffffu, s0, 2);
            s1 += __shfl_xor_sync(0xffffffffu, s1, 1);
            s1 += __shfl_xor_sync(0xffffffffu, s1, 2);
            l0 = l0 * a0 + s0;  l1 = l1 * a1 + s1;
            m0r = mn0;          m1r = mn1;
            #pragma unroll
            for (int nt = 0; nt < 8; nt++) {
                o[nt][0] *= a0; o[nt][1] *= a0;
                o[nt][2] *= a1; o[nt][3] *= a1;
            }

            // ---- O += P @ V (fp16 k16, P packed straight from accums) ----
            #pragma unroll
            for (int s = 0; s < 4; s++) {
                unsigned int pa[4];
                pa[0] = packhf(sc[2 * s][0],     sc[2 * s][1]);
                pa[1] = packhf(sc[2 * s][2],     sc[2 * s][3]);
                pa[2] = packhf(sc[2 * s + 1][0], sc[2 * s + 1][1]);
                pa[3] = packhf(sc[2 * s + 1][2], sc[2 * s + 1][3]);
                #pragma unroll
                for (int nt = 0; nt < 8; nt++) {
                    unsigned int b0 = Vt[(8 * nt + g) * AW2 + 8 * s + tig];
                    unsigned int b1 = Vt[(8 * nt + g) * AW2 + 8 * s + 4 + tig];
                    mma16h(o[nt], pa, b0, b1);
                }
            }
        }
        __syncthreads();
    }

    // epilogue: normalize + write packed f16x2 O (feeds proj GEMM)
    float inv0 = 1.f / l0, inv1 = 1.f / l1;
    const size_t row0 = (size_t)b * NSEQ + q0 + rw + g;
    #pragma unroll
    for (int nt = 0; nt < 8; nt++) {
        int cw = h * (HD / 2) + 4 * nt + tig;
        g_op[row0 * KW + cw]       = packhf(o[nt][0] * inv0, o[nt][1] * inv0);
        g_op[(row0 + 8) * KW + cw] = packhf(o[nt][2] * inv1, o[nt][3] * inv1);
    }
}

// ---------------------------------------------------------------------------
extern "C" void kernel_launch(void* const* d_in, const int* in_sizes, int n_in,
                              void* d_out, int out_size)
{
    const float *x = nullptr, *qkv_w = nullptr, *qkv_b = nullptr;
    const float *out_w = nullptr, *out_b = nullptr;
    for (int i = 0; i < n_in; i++) {
        switch (in_sizes[i]) {
            case M_ROWS * EMBED:    x     = (const float*)d_in[i]; break;
            case EMBED * QKV_COLS:  qkv_w = (const float*)d_in[i]; break;
            case QKV_COLS:          qkv_b = (const float*)d_in[i]; break;
            case EMBED * EMBED:     out_w = (const float*)d_in[i]; break;
            case EMBED:             out_b = (const float*)d_in[i]; break;
            default: break;   // causal mask ignored (tril hardcoded)
        }
    }
    float* out = (float*)d_out;

    unsigned int *xp, *wqp, *wop, *op;
    cudaGetSymbolAddress((void**)&xp,  g_xp);
    cudaGetSymbolAddress((void**)&wqp, g_wqp);
    cudaGetSymbolAddress((void**)&wop, g_wop);
    cudaGetSymbolAddress((void**)&op,  g_op);

    static bool attr_done = false;
    if (!attr_done) {
        cudaFuncSetAttribute(attn_f16,
                             cudaFuncAttributeMaxDynamicSharedMemorySize, ATT_SMEM);
        attr_done = true;
    }

    // 0) pack inputs to f16x2
    pack_f16<<<(M_ROWS * EMBED / 4) / 256, 256>>>(x, xp, M_ROWS * EMBED / 4);
    pack_f16<<<(QKV_COLS * EMBED / 4) / 256, 256>>>(qkv_w, wqp, QKV_COLS * EMBED / 4);
    pack_f16<<<(EMBED * EMBED / 4) / 256, 256>>>(out_w, wop, EMBED * EMBED / 4);

    // 1) QKV projection -> Q,K packed f16x2; V transposed f16x2
    gemm_f16<1><<<dim3(M_ROWS / 128, QKV_COLS / 128), 256, GEMM_SMEM>>>(
        xp, wqp, qkv_b, nullptr, QKV_COLS, KW);

    // 2) Causal flash attention -> packed f16x2 g_op
    attn_f16<<<dim3(NSEQ / 128, HEADS, BB), 256, ATT_SMEM>>>();

    // 3) Output projection -> d_out (f32)
    gemm_f16<0><<<dim3(M_ROWS / 128, EMBED / 128), 256, GEMM_SMEM>>>(
        op, wop, out_b, out, EMBED, KW);
}